// round 14
// baseline (speedup 1.0000x reference)
#include <cuda_runtime.h>
#include <cuda_bf16.h>
#include <math.h>
#include <stdint.h>

#define BB 16
#define CIN 20
#define HH 256
#define WW 256
#define WID 64
#define M1V 16
#define M2V 16
#define NLAY 4
#define FCH 128
#define CO 20
#define HW 65536
#define NPIX (BB*HW)

#define TWO_PI 6.28318530717958647692f

typedef unsigned long long ull;

// ---------------- scratch (device globals; no allocations allowed) ----------------
__device__ float  g_h0[(size_t)BB*WID*HW];            // 268 MB ping
__device__ float  g_h1[(size_t)BB*WID*HW];            // 268 MB pong
__device__ float2 g_Fw[(size_t)BB*WID*HH*M2V];        // (b,c,h,ky)  33.5 MB
__device__ float2 g_Fm[(size_t)BB*WID*32*M2V];        // (b,c,kxi,ky) 4 MB
__device__ float2 g_Gm[(size_t)BB*WID*32*M2V];        // 4 MB
__device__ float2 g_Gw[(size_t)BB*WID*HH*M2V];        // (b,c,h,ky)  33.5 MB
__device__ float2 g_Wt[(size_t)NLAY*512*WID*WID];     // (l,m,i,o)   67 MB
// bf16 prepped tables (pre-swizzled byte layouts)
__device__ __align__(16) unsigned char g_TsbH[16384]; // synth T hi: [px][32k] SW64
__device__ __align__(16) unsigned char g_TsbL[16384]; // synth T lo
__device__ __align__(16) unsigned char g_WbH[NLAY*8192]; // conv W hi: [och][64ch] SW128
__device__ __align__(16) unsigned char g_WbL[NLAY*8192];
__device__ __align__(16) unsigned char g_W1bH[16384]; // fc1 W hi: [128j][64ch] SW128
__device__ __align__(16) unsigned char g_W1bL[16384];
__device__ __align__(16) unsigned char g_TwbH[16384]; // dftw T hi: [kt][32n][64w] SW128
__device__ __align__(16) unsigned char g_TwbL[16384];
__device__ __align__(16) unsigned char g_ThfH[32768]; // dfth A: [kt][64m][64h] SW128 (m<32 cos, m>=32 -sin)
__device__ __align__(16) unsigned char g_ThfL[32768];
__device__ __align__(16) unsigned char g_TihH[32768]; // idfth A: [256h][64k] SW128 (k<32 cos, k>=32 +sin)
__device__ __align__(16) unsigned char g_TihL[32768];

// ---- packed f32x2 helpers ----
__device__ __forceinline__ ull ff2(ull a, ull b, ull c) {
    ull d; asm("fma.rn.f32x2 %0,%1,%2,%3;" : "=l"(d) : "l"(a), "l"(b), "l"(c)); return d;
}
__device__ __forceinline__ ull pk(float x, float y) {
    ull d; asm("mov.b64 %0,{%1,%2};" : "=l"(d) : "f"(x), "f"(y)); return d;
}
__device__ __forceinline__ float2 upk(ull u) {
    float2 f; asm("mov.b64 {%0,%1},%2;" : "=f"(f.x), "=f"(f.y) : "l"(u)); return f;
}

// ---- fast erf-based gelu ----
__device__ __forceinline__ float gelu_fast(float v) {
    float z  = 0.70710678118654752440f * v;
    float az = fabsf(z);
    float t  = __fdividef(1.0f, fmaf(0.3275911f, az, 1.0f));
    float e  = __expf(-az * az);
    float p  = t * (0.254829592f + t * (-0.284496736f + t * (1.421413741f +
               t * (-1.453152027f + t * 1.061405429f))));
    float er = fmaf(-p, e, 1.0f);
    er = copysignf(er, z);
    return 0.5f * v * (1.0f + er);
}

#define SW128(x) ((x) ^ (((x) >> 3) & 0x70))
#define SW64(x)  ((x) ^ (((x) >> 3) & 0x30))

__device__ __forceinline__ uint32_t smem_u32(const void* p) {
    uint32_t a;
    asm("{ .reg .u64 t; cvta.to.shared.u64 t, %1; cvt.u32.u64 %0, t; }" : "=r"(a) : "l"(p));
    return a;
}
__device__ __forceinline__ void ldsm4(uint32_t& r0, uint32_t& r1, uint32_t& r2, uint32_t& r3,
                                      uint32_t a) {
    asm volatile("ldmatrix.sync.aligned.m8n8.x4.shared.b16 {%0,%1,%2,%3}, [%4];"
                 : "=r"(r0), "=r"(r1), "=r"(r2), "=r"(r3) : "r"(a));
}
__device__ __forceinline__ void mma16816(float* c, const uint32_t* a, const uint32_t* b) {
    asm volatile(
        "mma.sync.aligned.m16n8k16.row.col.f32.bf16.bf16.f32 "
        "{%0,%1,%2,%3}, {%4,%5,%6,%7}, {%8,%9}, {%0,%1,%2,%3};"
        : "+f"(c[0]), "+f"(c[1]), "+f"(c[2]), "+f"(c[3])
        : "r"(a[0]), "r"(a[1]), "r"(a[2]), "r"(a[3]), "r"(b[0]), "r"(b[1]));
}
// split fp32 pair -> bf16x2 hi pair + lo pair
__device__ __forceinline__ void split2(float xa, float xb, uint32_t& hp, uint32_t& lp) {
    asm("cvt.rn.bf16x2.f32 %0, %1, %2;" : "=r"(hp) : "f"(xb), "f"(xa));
    float ha = __uint_as_float(hp << 16);
    float hb = __uint_as_float(hp & 0xFFFF0000u);
    float la = xa - ha, lb = xb - hb;
    asm("cvt.rn.bf16x2.f32 %0, %1, %2;" : "=r"(lp) : "f"(lb), "f"(la));
}
__device__ __forceinline__ void split1(float v, __nv_bfloat16& hi, __nv_bfloat16& lo) {
    hi = __float2bfloat16_rn(v);
    lo = __float2bfloat16_rn(v - __bfloat162float(hi));
}

// ---------------- twiddle init (synthesis table) ----------------
__global__ void k_twiddle() {
    int idx = blockIdx.x * blockDim.x + threadIdx.x;   // 8192 threads
    if (idx < 8192) {
        int px = idx >> 5, k = idx & 31;
        int ky = k & 15;
        int ph = (ky * px) & 255;
        float s, c;
        sincosf(TWO_PI * (float)ph * (1.0f / 256.0f), &s, &c);
        float val = ((k < 16) ? c : s) * (1.0f / 65536.0f);
        __nv_bfloat16 hi, lo; split1(val, hi, lo);
        uint32_t off = SW64((uint32_t)(px * 64 + k * 2));
        *(__nv_bfloat16*)(g_TsbH + off) = hi;
        *(__nv_bfloat16*)(g_TsbL + off) = lo;
    }
}

// ---------------- prep: fc1 weight split + dftw twiddle split ----------------
__global__ void k_prep2(const float* __restrict__ w1) {
    int idx = blockIdx.x * 256 + threadIdx.x;   // 8192
    {   // fc1 weights [128j][64ch] -> SW128 bf16 hi/lo
        int j = idx >> 6, ch = idx & 63;
        float v = w1[idx];
        __nv_bfloat16 hi, lo; split1(v, hi, lo);
        uint32_t off = SW128((uint32_t)(j * 128 + ch * 2));
        *(__nv_bfloat16*)(g_W1bH + off) = hi;
        *(__nv_bfloat16*)(g_W1bL + off) = lo;
    }
    {   // dftw twiddles: n<16: cos(theta); n>=16: -sin(theta)
        int n = idx >> 8, w = idx & 255;
        int ky = n & 15;
        int ph = (ky * w) & 255;
        float s, c;
        sincosf(-TWO_PI * (float)ph * (1.0f / 256.0f), &s, &c);
        float val = (n < 16) ? c : s;
        __nv_bfloat16 hi, lo; split1(val, hi, lo);
        uint32_t off = (uint32_t)(w >> 6) * 4096 + SW128((uint32_t)(n * 128 + (w & 63) * 2));
        *(__nv_bfloat16*)(g_TwbH + off) = hi;
        *(__nv_bfloat16*)(g_TwbL + off) = lo;
    }
}

// ---------------- prep: dfth / idfth twiddle A-tables ----------------
__global__ void k_prep3() {
    int idx = blockIdx.x * 256 + threadIdx.x;   // 16384
    {   // dfth A: [kt][64m][64h] SW128; m<32 -> cos, m>=32 -> -sin (Tfh convention)
        int m = idx >> 8, h = idx & 255;
        int kxi = m & 31, part = m >> 5;
        int kx = (kxi < 16) ? kxi : (224 + kxi);
        int ph = (kx * h) & 255;
        float s, c;
        sincosf(-TWO_PI * (float)ph * (1.0f / 256.0f), &s, &c);   // s = -sin
        float val = part ? s : c;
        __nv_bfloat16 hi, lo; split1(val, hi, lo);
        uint32_t off = (uint32_t)(h >> 6) * 8192 + SW128((uint32_t)(m * 128 + (h & 63) * 2));
        *(__nv_bfloat16*)(g_ThfH + off) = hi;
        *(__nv_bfloat16*)(g_ThfL + off) = lo;
    }
    {   // idfth A: [256h][64k] SW128; k<32 -> cos, k>=32 -> +sin (Tih convention)
        int h = idx >> 6, k = idx & 63;
        int kxi = k & 31, part = k >> 5;
        int kx = (kxi < 16) ? kxi : (224 + kxi);
        int ph = (kx * h) & 255;
        float s, c;
        sincosf(TWO_PI * (float)ph * (1.0f / 256.0f), &s, &c);    // s = +sin
        float val = part ? s : c;
        __nv_bfloat16 hi, lo; split1(val, hi, lo);
        uint32_t off = SW128((uint32_t)(h * 128 + k * 2));
        *(__nv_bfloat16*)(g_TihH + off) = hi;
        *(__nv_bfloat16*)(g_TihL + off) = lo;
    }
}

// ---------------- conv-weight bf16 prep ----------------
__global__ void k_wbprep(const float* __restrict__ pww) {
    int tid = blockIdx.x * 256 + threadIdx.x;          // < NLAY*4096
    int l = tid >> 12, r = tid & 4095;
    int och = r >> 6, ch = r & 63;
    float w = pww[l * 4096 + och * 64 + ch];
    __nv_bfloat16 hi, lo; split1(w, hi, lo);
    uint32_t off = SW128((uint32_t)(och * 128 + ch * 2));
    *(__nv_bfloat16*)(g_WbH + l * 8192 + off) = hi;
    *(__nv_bfloat16*)(g_WbL + l * 8192 + off) = lo;
}

// ---------------- spectral-weight transpose ----------------
__global__ void k_wt(const float* __restrict__ w1r, const float* __restrict__ w1i,
                     const float* __restrict__ w2r, const float* __restrict__ w2i) {
    int tid = blockIdx.x * blockDim.x + threadIdx.x;
    if (tid >= NLAY * 512 * WID * WID) return;
    int o   = tid & 63;
    int i   = (tid >> 6) & 63;
    int m   = (tid >> 12) & 511;
    int l   = tid >> 21;
    int kxi = m >> 4;
    int ky  = m & 15;
    int kk  = (kxi & 15) * 16 + ky;
    size_t src = ((size_t)(l * 64 + i) * 64 + o) * 256 + kk;
    float r, im;
    if (kxi < 16) { r = w1r[src]; im = w1i[src]; }
    else          { r = w2r[src]; im = w2i[src]; }
    g_Wt[tid] = make_float2(r, im);
}

// ---------------- fc0 lift ----------------
__global__ void __launch_bounds__(256) k_fc0(const float* __restrict__ x,
                                             const float* __restrict__ w,
                                             const float* __restrict__ bias) {
    __shared__ ull wp[CIN * 32];
    __shared__ ull bp[32];
    int t = threadIdx.x;
    for (int k = t; k < CIN * 32; k += 256) {
        int d2 = k & 31, c = k >> 5;
        wp[c * 32 + d2] = pk(w[(2 * d2) * CIN + c], w[(2 * d2 + 1) * CIN + c]);
    }
    if (t < 32) bp[t] = pk(bias[2 * t], bias[2 * t + 1]);
    __syncthreads();
    int p  = blockIdx.x * 256 + t;
    int b  = p >> 16;
    int sp = p & 65535;
    ull xx[CIN];
#pragma unroll
    for (int c = 0; c < CIN; c++) {
        float v = x[((size_t)(b * CIN + c) << 16) + sp];
        xx[c] = pk(v, v);
    }
#pragma unroll
    for (int d2 = 0; d2 < 32; d2++) {
        ull a = bp[d2];
#pragma unroll
        for (int c = 0; c < CIN; c++) a = ff2(xx[c], wp[c * 32 + d2], a);
        float2 f = upk(a);
        g_h0[((size_t)(b * WID + 2 * d2) << 16) + sp]     = f.x;
        g_h0[((size_t)(b * WID + 2 * d2 + 1) << 16) + sp] = f.y;
    }
}

// ============ k_dftw_mma (R13, verified) ============
__global__ void __launch_bounds__(256)
k_dftw_mma(const float* __restrict__ hin) {
    extern __shared__ char smx[];
    const uint32_t sb = smem_u32(smx);
    int t = threadIdx.x;
    size_t rbase = (size_t)blockIdx.x * 256;

    {
        const ulonglong2* srcH = (const ulonglong2*)g_TwbH;
        const ulonglong2* srcL = (const ulonglong2*)g_TwbL;
        ulonglong2* dstH = (ulonglong2*)(smx + 65536);
        ulonglong2* dstL = (ulonglong2*)(smx + 81920);
        for (int k = t; k < 1024; k += 256) { dstH[k] = srcH[k]; dstL[k] = srcL[k]; }
    }

    const int lane = t & 31;
    const int wrp  = t >> 5;
    const int pxb  = wrp * 32;
    const int grp = lane >> 3, rr = lane & 7;
    const int a_m = ((grp & 1) << 3) + rr;
    const int a_k = (grp >> 1) << 3;
    const int b_n = ((grp >> 1) << 3) + rr;
    const int b_k = (grp & 1) << 3;

    float acc[32];
#pragma unroll
    for (int i = 0; i < 32; i++) acc[i] = 0.0f;

    for (int kt = 0; kt < 4; kt++) {
        __syncthreads();
        for (int k = t; k < 8192; k += 256) {
            int row = k >> 5, p2 = k & 31;
            const float* xp = hin + (rbase + row) * 256 + kt * 64 + 2 * p2;
            uint32_t hp, lp;
            split2(xp[0], xp[1], hp, lp);
            uint32_t off = SW128((uint32_t)(row * 128 + p2 * 4));
            *(uint32_t*)(smx + off)         = hp;
            *(uint32_t*)(smx + 32768 + off) = lp;
        }
        __syncthreads();
#pragma unroll
        for (int kc = 0; kc < 4; kc++) {
            int kb = kc * 16;
            uint32_t ah[2][4], al[2][4];
#pragma unroll
            for (int mt = 0; mt < 2; mt++) {
                uint32_t aoff = SW128((uint32_t)((pxb + mt * 16 + a_m) * 128 + (kb + a_k) * 2));
                ldsm4(ah[mt][0], ah[mt][1], ah[mt][2], ah[mt][3], sb + aoff);
                ldsm4(al[mt][0], al[mt][1], al[mt][2], al[mt][3], sb + 32768 + aoff);
            }
#pragma unroll
            for (int jp = 0; jp < 2; jp++) {
                uint32_t bh[4], bl[4];
                uint32_t boff = (uint32_t)kt * 4096 +
                                SW128((uint32_t)((jp * 16 + b_n) * 128 + (kb + b_k) * 2));
                ldsm4(bh[0], bh[1], bh[2], bh[3], sb + 65536 + boff);
                ldsm4(bl[0], bl[1], bl[2], bl[3], sb + 81920 + boff);
#pragma unroll
                for (int mt = 0; mt < 2; mt++) {
#pragma unroll
                    for (int ntl = 0; ntl < 2; ntl++) {
                        float* c = &acc[(mt * 4 + jp * 2 + ntl) * 4];
                        mma16816(c, ah[mt], &bh[ntl * 2]);
                        mma16816(c, ah[mt], &bl[ntl * 2]);
                        mma16816(c, al[mt], &bh[ntl * 2]);
                    }
                }
            }
        }
    }

    int g = lane >> 2, tq = lane & 3;
#pragma unroll
    for (int mt = 0; mt < 2; mt++) {
#pragma unroll
        for (int n8 = 0; n8 < 2; n8++) {
#pragma unroll
            for (int c = 0; c < 4; c++) {
                int row = pxb + mt * 16 + g + ((c >> 1) << 3);
                int ky  = n8 * 8 + tq * 2 + (c & 1);
                float re = acc[(mt * 4 + n8) * 4 + c];
                float im = acc[(mt * 4 + n8 + 2) * 4 + c];
                g_Fw[(rbase + row) * 16 + ky] = make_float2(re, im);
            }
        }
    }
}

// ============ k_dfth_mma: h-DFT as HMMA GEMM ============
// per bc: C[64 x 32] = A[64 x 256] * B[256 x 32]; A = [cos; -sin] (static), B = [Fr|Fi].
// smem: 0 BH [kt][32n][64h] 16384 | 16384 BL | 32768 AH [kt][64m][64h] 32768 | 65536 AL
// total 98304. Stage C (64*33 floats = 8448 B) overlaps at 0 after mma.
__global__ void __launch_bounds__(256)
k_dfth_mma() {
    extern __shared__ char smx[];
    const uint32_t sb = smem_u32(smx);
    int t = threadIdx.x;
    int bc = blockIdx.x;

    // stage A tables (64 KB)
    {
        const ulonglong2* srcH = (const ulonglong2*)g_ThfH;
        const ulonglong2* srcL = (const ulonglong2*)g_ThfL;
        ulonglong2* dstH = (ulonglong2*)(smx + 32768);
        ulonglong2* dstL = (ulonglong2*)(smx + 65536);
        for (int k = t; k < 2048; k += 256) { dstH[k] = srcH[k]; dstL[k] = srcL[k]; }
    }
    // stage B: Fw -> [kt][32n][64h], n<16: Fr(row ky), n>=16: Fi
    for (int k = t; k < 4096; k += 256) {
        int h = k >> 4, ky = k & 15;
        float2 f = g_Fw[(size_t)bc * 4096 + k];
        __nv_bfloat16 hr, lr, hi2, li2;
        split1(f.x, hr, lr);
        split1(f.y, hi2, li2);
        uint32_t cb = (uint32_t)(h >> 6) * 4096;
        uint32_t o1 = cb + SW128((uint32_t)(ky * 128 + (h & 63) * 2));
        uint32_t o2 = cb + SW128((uint32_t)((16 + ky) * 128 + (h & 63) * 2));
        *(__nv_bfloat16*)(smx + o1)         = hr;
        *(__nv_bfloat16*)(smx + 16384 + o1) = lr;
        *(__nv_bfloat16*)(smx + o2)         = hi2;
        *(__nv_bfloat16*)(smx + 16384 + o2) = li2;
    }
    __syncthreads();

    const int lane = t & 31;
    const int wrp  = t >> 5;
    const int mt   = wrp & 3;       // m-tile (16 rows of 64)
    const int nh   = wrp >> 2;      // n-half (16 cols of 32)
    const int grp = lane >> 3, rr = lane & 7;
    const int a_m = ((grp & 1) << 3) + rr;
    const int a_k = (grp >> 1) << 3;
    const int b_n = ((grp >> 1) << 3) + rr;
    const int b_k = (grp & 1) << 3;

    float acc[2][4];
#pragma unroll
    for (int i = 0; i < 2; i++)
#pragma unroll
        for (int c = 0; c < 4; c++) acc[i][c] = 0.0f;

#pragma unroll
    for (int k16 = 0; k16 < 16; k16++) {
        int kt = k16 >> 2, kb = (k16 & 3) * 16;
        uint32_t ah[4], al[4], bh[4], bl[4];
        uint32_t aoff = (uint32_t)kt * 8192 +
                        SW128((uint32_t)((mt * 16 + a_m) * 128 + (kb + a_k) * 2));
        ldsm4(ah[0], ah[1], ah[2], ah[3], sb + 32768 + aoff);
        ldsm4(al[0], al[1], al[2], al[3], sb + 65536 + aoff);
        uint32_t boff = (uint32_t)kt * 4096 +
                        SW128((uint32_t)((nh * 16 + b_n) * 128 + (kb + b_k) * 2));
        ldsm4(bh[0], bh[1], bh[2], bh[3], sb + boff);
        ldsm4(bl[0], bl[1], bl[2], bl[3], sb + 16384 + boff);
#pragma unroll
        for (int ntl = 0; ntl < 2; ntl++) {
            float* c = acc[ntl];
            mma16816(c, ah, &bh[ntl * 2]);
            mma16816(c, ah, &bl[ntl * 2]);
            mma16816(c, al, &bh[ntl * 2]);
        }
    }

    __syncthreads();
    // stage C [64][33]
    {
        float* stage = (float*)smx;
        int g = lane >> 2, tq = lane & 3;
#pragma unroll
        for (int ntl = 0; ntl < 2; ntl++) {
#pragma unroll
            for (int c = 0; c < 4; c++) {
                int row = mt * 16 + g + ((c >> 1) << 3);
                int col = nh * 16 + ntl * 8 + tq * 2 + (c & 1);
                stage[row * 33 + col] = acc[ntl][c];
            }
        }
    }
    __syncthreads();
    {
        const float* stage = (const float*)smx;
#pragma unroll
        for (int mm = 0; mm < 2; mm++) {
            int m = t + mm * 256;
            int kxi = m >> 4, ky = m & 15;
            float re = stage[kxi * 33 + ky]        - stage[(32 + kxi) * 33 + 16 + ky];
            float im = stage[kxi * 33 + 16 + ky]   + stage[(32 + kxi) * 33 + ky];
            g_Fm[(size_t)bc * 512 + m] = make_float2(re, im);
        }
    }
}

// ---------------- channel mixing (R5) ----------------
__global__ void k_mix(int layer) {
    __shared__ float2 Wm[WID * WID];
    __shared__ float2 Fsh[BB * WID];
    int t = threadIdx.x;
    int m = blockIdx.x;
    const float2* wsrc = g_Wt + ((size_t)layer * 512 + m) * 4096;
    for (int k = t; k < 4096; k += 256) Wm[k] = wsrc[k];
    for (int k = t; k < 1024; k += 256) {
        int b = k >> 6, i = k & 63;
        Fsh[k] = g_Fm[(size_t)(b * 64 + i) * 512 + m];
    }
    __syncthreads();
#pragma unroll
    for (int u = 0; u < 4; u++) {
        int outi = t + u * 256;
        int b = outi >> 6, o = outi & 63;
        float sr = 0.f, si = 0.f;
#pragma unroll 8
        for (int i = 0; i < 64; i++) {
            float2 f = Fsh[b * 64 + i];
            float2 w = Wm[i * 64 + o];
            sr = fmaf(f.x, w.x, fmaf(-f.y, w.y, sr));
            si = fmaf(f.x, w.y, fmaf( f.y, w.x, si));
        }
        g_Gm[(size_t)(b * 64 + o) * 512 + m] = make_float2(sr, si);
    }
}

// ============ k_idfth_mma: inverse h-transform as HMMA GEMM ============
// per bc: C[256h x 32] = A[256 x 64] * B[64 x 32]; A = [cos | +sin] (static),
// B rows: n=ky: [Gr; -Gi], n=16+ky: [Gi; Gr]. C[:,0:16]=Gw_re, C[:,16:32]=Gw_im.
// smem: 0 AH 32768 | 32768 AL 32768 | 65536 BH 4096 | 69632 BL 4096 = 73728
__global__ void __launch_bounds__(256)
k_idfth_mma() {
    extern __shared__ char smx[];
    const uint32_t sb = smem_u32(smx);
    int t = threadIdx.x;
    int bc = blockIdx.x;

    {
        const ulonglong2* srcH = (const ulonglong2*)g_TihH;
        const ulonglong2* srcL = (const ulonglong2*)g_TihL;
        ulonglong2* dstH = (ulonglong2*)smx;
        ulonglong2* dstL = (ulonglong2*)(smx + 32768);
        for (int k = t; k < 2048; k += 256) { dstH[k] = srcH[k]; dstL[k] = srcL[k]; }
    }
    // stage B from g_Gm
    for (int k = t; k < 512; k += 256) {
        int kxi = k >> 4, ky = k & 15;
        float2 g = g_Gm[(size_t)bc * 512 + k];
        __nv_bfloat16 hr, lr, hi2, li2, hnr, lnr;
        split1(g.x, hr, lr);         // Gr
        split1(g.y, hi2, li2);       // Gi
        split1(-g.y, hnr, lnr);      // -Gi
        uint32_t o_rk  = SW128((uint32_t)(ky * 128 + kxi * 2));            // (ky, kxi) <- Gr
        uint32_t o_rni = SW128((uint32_t)(ky * 128 + (32 + kxi) * 2));     // (ky, 32+kxi) <- -Gi
        uint32_t o_ik  = SW128((uint32_t)((16 + ky) * 128 + kxi * 2));     // (16+ky, kxi) <- Gi
        uint32_t o_ir  = SW128((uint32_t)((16 + ky) * 128 + (32 + kxi) * 2)); // <- Gr
        *(__nv_bfloat16*)(smx + 65536 + o_rk)  = hr;
        *(__nv_bfloat16*)(smx + 69632 + o_rk)  = lr;
        *(__nv_bfloat16*)(smx + 65536 + o_rni) = hnr;
        *(__nv_bfloat16*)(smx + 69632 + o_rni) = lnr;
        *(__nv_bfloat16*)(smx + 65536 + o_ik)  = hi2;
        *(__nv_bfloat16*)(smx + 69632 + o_ik)  = li2;
        *(__nv_bfloat16*)(smx + 65536 + o_ir)  = hr;
        *(__nv_bfloat16*)(smx + 69632 + o_ir)  = lr;
    }
    __syncthreads();

    const int lane = t & 31;
    const int wrp  = t >> 5;
    const int hbase = wrp * 32;
    const int grp = lane >> 3, rr = lane & 7;
    const int a_m = ((grp & 1) << 3) + rr;
    const int a_k = (grp >> 1) << 3;
    const int b_n = ((grp >> 1) << 3) + rr;
    const int b_k = (grp & 1) << 3;

    float acc[2][4][4];
#pragma unroll
    for (int mt = 0; mt < 2; mt++)
#pragma unroll
        for (int n8 = 0; n8 < 4; n8++)
#pragma unroll
            for (int c = 0; c < 4; c++) acc[mt][n8][c] = 0.0f;

#pragma unroll
    for (int kt = 0; kt < 4; kt++) {
        int kb = kt * 16;
        uint32_t ah[2][4], al[2][4];
#pragma unroll
        for (int mt = 0; mt < 2; mt++) {
            uint32_t aoff = SW128((uint32_t)((hbase + mt * 16 + a_m) * 128 + (kb + a_k) * 2));
            ldsm4(ah[mt][0], ah[mt][1], ah[mt][2], ah[mt][3], sb + aoff);
            ldsm4(al[mt][0], al[mt][1], al[mt][2], al[mt][3], sb + 32768 + aoff);
        }
#pragma unroll
        for (int jp = 0; jp < 2; jp++) {
            uint32_t bh[4], bl[4];
            uint32_t boff = SW128((uint32_t)((jp * 16 + b_n) * 128 + (kb + b_k) * 2));
            ldsm4(bh[0], bh[1], bh[2], bh[3], sb + 65536 + boff);
            ldsm4(bl[0], bl[1], bl[2], bl[3], sb + 69632 + boff);
#pragma unroll
            for (int mt = 0; mt < 2; mt++) {
#pragma unroll
                for (int ntl = 0; ntl < 2; ntl++) {
                    float* c = acc[mt][jp * 2 + ntl];
                    mma16816(c, ah[mt], &bh[ntl * 2]);
                    mma16816(c, ah[mt], &bl[ntl * 2]);
                    mma16816(c, al[mt], &bh[ntl * 2]);
                }
            }
        }
    }

    // write fragments directly: re at col ky (n8=a), im at col 16+ky (n8=a+2)
    int g = lane >> 2, tq = lane & 3;
#pragma unroll
    for (int mt = 0; mt < 2; mt++) {
#pragma unroll
        for (int a = 0; a < 2; a++) {
#pragma unroll
            for (int c = 0; c < 4; c++) {
                int row = hbase + mt * 16 + g + ((c >> 1) << 3);
                int ky  = a * 8 + tq * 2 + (c & 1);
                float re = acc[mt][a][c];
                float im = acc[mt][a + 2][c];
                g_Gw[((size_t)bc * 256 + row) * 16 + ky] = make_float2(re, im);
            }
        }
    }
}

// ============ k_fused_mma (R12, verified) ============
__global__ void __launch_bounds__(256)
k_fused_mma(const float* __restrict__ hin, float* __restrict__ hout,
            int layer, const float* __restrict__ pwb, int dogelu) {
    extern __shared__ char smx[];
    const uint32_t sb = smem_u32(smx);
    int t = threadIdx.x;
    int b = blockIdx.x >> 8, row = blockIdx.x & 255;

    {
        const float* xp = hin + ((size_t)(b * 64) << 16) + row * 256 + t;
#pragma unroll
        for (int i2 = 0; i2 < 32; i2++) {
            float xa = xp[(size_t)(2 * i2) << 16];
            float xb = xp[(size_t)(2 * i2 + 1) << 16];
            uint32_t hp, lp;
            split2(xa, xb, hp, lp);
            uint32_t off = SW128((uint32_t)(t * 128 + i2 * 4));
            *(uint32_t*)(smx + off)         = hp;
            *(uint32_t*)(smx + 32768 + off) = lp;
        }
    }
    {
        const ulonglong2* srcH = (const ulonglong2*)(g_WbH + layer * 8192);
        const ulonglong2* srcL = (const ulonglong2*)(g_WbL + layer * 8192);
        ulonglong2* dstH = (ulonglong2*)(smx + 65536);
        ulonglong2* dstL = (ulonglong2*)(smx + 73728);
        for (int k = t; k < 512; k += 256) { dstH[k] = srcH[k]; dstL[k] = srcL[k]; }
    }
    {
        const ulonglong2* srcH = (const ulonglong2*)g_TsbH;
        const ulonglong2* srcL = (const ulonglong2*)g_TsbL;
        ulonglong2* dstH = (ulonglong2*)(smx + 81920);
        ulonglong2* dstL = (ulonglong2*)(smx + 98304);
        for (int k = t; k < 1024; k += 256) { dstH[k] = srcH[k]; dstL[k] = srcL[k]; }
    }
    for (int k = t; k < 1024; k += 256) {
        int och = k >> 4, ky = k & 15;
        float2 g = g_Gw[(((size_t)(b * 64 + och)) * 256 + row) * 16 + ky];
        float vx = (ky == 0) ? g.x : 2.0f * g.x;
        float vy = (ky == 0) ? 0.0f : -2.0f * g.y;
        __nv_bfloat16 hx, lx, hy, ly;
        split1(vx, hx, lx);
        split1(vy, hy, ly);
        uint32_t off1 = SW64((uint32_t)(och * 64 + ky * 2));
        uint32_t off2 = SW64((uint32_t)(och * 64 + (16 + ky) * 2));
        *(__nv_bfloat16*)(smx + 114688 + off1) = hx;
        *(__nv_bfloat16*)(smx + 118784 + off1) = lx;
        *(__nv_bfloat16*)(smx + 114688 + off2) = hy;
        *(__nv_bfloat16*)(smx + 118784 + off2) = ly;
    }
    if (t < 64) ((float*)(smx + 122880))[t] = pwb[t];
    __syncthreads();

    const int lane = t & 31;
    const int wrp  = t >> 5;
    const int pxb  = wrp * 32;
    const int grp = lane >> 3, rr = lane & 7;
    const int a_m = ((grp & 1) << 3) + rr;
    const int a_k = (grp >> 1) << 3;
    const int b_n = ((grp >> 1) << 3) + rr;
    const int b_k = (grp & 1) << 3;

    float acc[2][8][4];
#pragma unroll
    for (int mt = 0; mt < 2; mt++)
#pragma unroll
        for (int n8 = 0; n8 < 8; n8++)
#pragma unroll
            for (int c = 0; c < 4; c++) acc[mt][n8][c] = 0.0f;

#pragma unroll
    for (int kt = 0; kt < 4; kt++) {
        int kb = kt * 16;
        uint32_t ah[2][4], al[2][4];
#pragma unroll
        for (int mt = 0; mt < 2; mt++) {
            uint32_t aoff = SW128((uint32_t)((pxb + mt * 16 + a_m) * 128 + (kb + a_k) * 2));
            ldsm4(ah[mt][0], ah[mt][1], ah[mt][2], ah[mt][3], sb + aoff);
            ldsm4(al[mt][0], al[mt][1], al[mt][2], al[mt][3], sb + 32768 + aoff);
        }
#pragma unroll
        for (int jp = 0; jp < 4; jp++) {
            int nb = jp * 16;
            uint32_t bh[4], bl[4];
            uint32_t boff = SW128((uint32_t)((nb + b_n) * 128 + (kb + b_k) * 2));
            ldsm4(bh[0], bh[1], bh[2], bh[3], sb + 65536 + boff);
            ldsm4(bl[0], bl[1], bl[2], bl[3], sb + 73728 + boff);
#pragma unroll
            for (int mt = 0; mt < 2; mt++) {
#pragma unroll
                for (int ntl = 0; ntl < 2; ntl++) {
                    float* c = acc[mt][jp * 2 + ntl];
                    mma16816(c, ah[mt], &bh[ntl * 2]);
                    mma16816(c, ah[mt], &bl[ntl * 2]);
                    mma16816(c, al[mt], &bh[ntl * 2]);
                }
            }
        }
    }
#pragma unroll
    for (int kt = 0; kt < 2; kt++) {
        int kb = kt * 16;
        uint32_t ah[2][4], al[2][4];
#pragma unroll
        for (int mt = 0; mt < 2; mt++) {
            uint32_t aoff = SW64((uint32_t)((pxb + mt * 16 + a_m) * 64 + (kb + a_k) * 2));
            ldsm4(ah[mt][0], ah[mt][1], ah[mt][2], ah[mt][3], sb + 81920 + aoff);
            ldsm4(al[mt][0], al[mt][1], al[mt][2], al[mt][3], sb + 98304 + aoff);
        }
#pragma unroll
        for (int jp = 0; jp < 4; jp++) {
            int nb = jp * 16;
            uint32_t bh[4], bl[4];
            uint32_t boff = SW64((uint32_t)((nb + b_n) * 64 + (kb + b_k) * 2));
            ldsm4(bh[0], bh[1], bh[2], bh[3], sb + 114688 + boff);
            ldsm4(bl[0], bl[1], bl[2], bl[3], sb + 118784 + boff);
#pragma unroll
            for (int mt = 0; mt < 2; mt++) {
#pragma unroll
                for (int ntl = 0; ntl < 2; ntl++) {
                    float* c = acc[mt][jp * 2 + ntl];
                    mma16816(c, ah[mt], &bh[ntl * 2]);
                    mma16816(c, ah[mt], &bl[ntl * 2]);
                    mma16816(c, al[mt], &bh[ntl * 2]);
                }
            }
        }
    }

    __syncthreads();
    {
        float* stage = (float*)smx;
        const float* bsh = (const float*)(smx + 122880);
        int g = lane >> 2, tq = lane & 3;
#pragma unroll
        for (int mt = 0; mt < 2; mt++) {
            int px0 = pxb + mt * 16 + g;
#pragma unroll
            for (int n8 = 0; n8 < 8; n8++) {
                int och = n8 * 8 + tq * 2;
                float b0 = bsh[och], b1 = bsh[och + 1];
                float v00 = acc[mt][n8][0] + b0;
                float v01 = acc[mt][n8][1] + b1;
                float v10 = acc[mt][n8][2] + b0;
                float v11 = acc[mt][n8][3] + b1;
                if (dogelu) {
                    v00 = gelu_fast(v00); v01 = gelu_fast(v01);
                    v10 = gelu_fast(v10); v11 = gelu_fast(v11);
                }
                stage[och * 260 + px0]           = v00;
                stage[(och + 1) * 260 + px0]     = v01;
                stage[och * 260 + px0 + 8]       = v10;
                stage[(och + 1) * 260 + px0 + 8] = v11;
            }
        }
    }
    __syncthreads();
    {
        const float* stage = (const float*)smx;
        float* outp = hout + ((size_t)(b * 64) << 16) + row * 256 + t;
#pragma unroll 8
        for (int i = 0; i < 64; i++)
            outp[(size_t)i << 16] = stage[i * 260 + t];
    }
}

// ============ k_final_mma (R13, verified) ============
__global__ void __launch_bounds__(512)
k_final_mma(const float* __restrict__ hin, float* __restrict__ out,
            const float* __restrict__ b1, const float* __restrict__ w2,
            const float* __restrict__ b2) {
    extern __shared__ char smx[];
    const uint32_t sb = smem_u32(smx);
    int t = threadIdx.x;
    int b = blockIdx.x >> 8, row = blockIdx.x & 255;

    size_t base = ((size_t)(b * 64) << 16) + (size_t)row * 256;
    for (int k = t; k < 8192; k += 512) {
        int px = k & 255, i2 = k >> 8;
        float xa = hin[base + ((size_t)(2 * i2) << 16) + px];
        float xb = hin[base + ((size_t)(2 * i2 + 1) << 16) + px];
        uint32_t hp, lp;
        split2(xa, xb, hp, lp);
        uint32_t off = SW128((uint32_t)(px * 128 + i2 * 4));
        *(uint32_t*)(smx + off)         = hp;
        *(uint32_t*)(smx + 32768 + off) = lp;
    }
    {
        const ulonglong2* srcH = (const ulonglong2*)g_W1bH;
        const ulonglong2* srcL = (const ulonglong2*)g_W1bL;
        ulonglong2* dstH = (ulonglong2*)(smx + 65536);
        ulonglong2* dstL = (ulonglong2*)(smx + 81920);
        for (int k = t; k < 1024; k += 512) { dstH[k] = srcH[k]; dstL[k] = srcL[k]; }
    }
    {
        ull* w2t = (ull*)(smx + 133120);
        for (int k = t; k < FCH * 10; k += 512) {
            int o2 = k >> 7, j = k & 127;
            w2t[j * 10 + o2] = pk(w2[(2 * o2) * FCH + j], w2[(2 * o2 + 1) * FCH + j]);
        }
    }
    if (t < FCH) ((float*)(smx + 143360))[t] = b1[t];
    if (t < 10)  ((ull*)(smx + 143872))[t] = pk(b2[2 * t], b2[2 * t + 1]);
    __syncthreads();

    const int lane = t & 31;
    const int wrp  = t >> 5;
    const int pxb  = wrp * 16;
    const int grp = lane >> 3, rr = lane & 7;
    const int a_m = ((grp & 1) << 3) + rr;
    const int a_k = (grp >> 1) << 3;
    const int b_n = ((grp >> 1) << 3) + rr;
    const int b_k = (grp & 1) << 3;

    float acc[64];
#pragma unroll
    for (int i = 0; i < 64; i++) acc[i] = 0.0f;

#pragma unroll
    for (int kt = 0; kt < 4; kt++) {
        int kb = kt * 16;
        uint32_t ah[4], al[4];
        uint32_t aoff = SW128((uint32_t)((pxb + a_m) * 128 + (kb + a_k) * 2));
        ldsm4(ah[0], ah[1], ah[2], ah[3], sb + aoff);
        ldsm4(al[0], al[1], al[2], al[3], sb + 32768 + aoff);
#pragma unroll
        for (int jp = 0; jp < 8; jp++) {
            uint32_t bh[4], bl[4];
            uint32_t boff = SW128((uint32_t)((jp * 16 + b_n) * 128 + (kb + b_k) * 2));
            ldsm4(bh[0], bh[1], bh[2], bh[3], sb + 65536 + boff);
            ldsm4(bl[0], bl[1], bl[2], bl[3], sb + 81920 + boff);
#pragma unroll
            for (int ntl = 0; ntl < 2; ntl++) {
                float* c = &acc[(jp * 2 + ntl) * 4];
                mma16816(c, ah, &bh[ntl * 2]);
                mma16816(c, ah, &bl[ntl * 2]);
                mma16816(c, al, &bh[ntl * 2]);
            }
        }
    }

    __syncthreads();
    {
        float* stage = (float*)smx;
        const float* b1sh = (const float*)(smx + 143360);
        int g = lane >> 2, tq = lane & 3;
        int px0 = pxb + g;
#pragma unroll
        for (int n8 = 0; n8 < 16; n8++) {
            int j0 = n8 * 8 + tq * 2;
            float bb0 = b1sh[j0], bb1 = b1sh[j0 + 1];
            stage[j0 * 260 + px0]           = gelu_fast(acc[n8 * 4 + 0] + bb0);
            stage[(j0 + 1) * 260 + px0]     = gelu_fast(acc[n8 * 4 + 1] + bb1);
            stage[j0 * 260 + px0 + 8]       = gelu_fast(acc[n8 * 4 + 2] + bb0);
            stage[(j0 + 1) * 260 + px0 + 8] = gelu_fast(acc[n8 * 4 + 3] + bb1);
        }
    }
    __syncthreads();
    {
        const float* stage = (const float*)smx;
        const ull* w2t = (const ull*)(smx + 133120);
        const ull* b2p = (const ull*)(smx + 143872);
        int px = t & 255;
        int oh = t >> 8;
        ull a5[5];
#pragma unroll
        for (int k = 0; k < 5; k++) a5[k] = b2p[oh * 5 + k];
        for (int j = 0; j < FCH; j++) {
            float hv = stage[j * 260 + px];
            ull hh = pk(hv, hv);
            const ull* wp = &w2t[j * 10 + oh * 5];
#pragma unroll
            for (int k = 0; k < 5; k++) a5[k] = ff2(hh, wp[k], a5[k]);
        }
        size_t sp = (size_t)row * 256 + px;
#pragma unroll
        for (int k = 0; k < 5; k++) {
            int o2 = oh * 5 + k;
            float2 a = upk(a5[k]);
            out[((size_t)(b * CO + 2 * o2) << 16) + sp]     = a.x;
            out[((size_t)(b * CO + 2 * o2 + 1) << 16) + sp] = a.y;
        }
    }
}

// ---------------- orchestration ----------------
extern "C" void kernel_launch(void* const* d_in, const int* in_sizes, int n_in,
                              void* d_out, int out_size) {
    const float* x    = (const float*)d_in[0];
    const float* w1r  = (const float*)d_in[1];
    const float* w1i  = (const float*)d_in[2];
    const float* w2r  = (const float*)d_in[3];
    const float* w2i  = (const float*)d_in[4];
    const float* pww  = (const float*)d_in[5];
    const float* pwb  = (const float*)d_in[6];
    const float* fc0w = (const float*)d_in[7];
    const float* fc0b = (const float*)d_in[8];
    const float* fc1w = (const float*)d_in[9];
    const float* fc1b = (const float*)d_in[10];
    const float* fc2w = (const float*)d_in[11];
    const float* fc2b = (const float*)d_in[12];
    float* out = (float*)d_out;

    cudaFuncSetAttribute(k_dftw_mma,  cudaFuncAttributeMaxDynamicSharedMemorySize, 98304);
    cudaFuncSetAttribute(k_dfth_mma,  cudaFuncAttributeMaxDynamicSharedMemorySize, 98304);
    cudaFuncSetAttribute(k_idfth_mma, cudaFuncAttributeMaxDynamicSharedMemorySize, 73728);
    cudaFuncSetAttribute(k_fused_mma, cudaFuncAttributeMaxDynamicSharedMemorySize, 123136);
    cudaFuncSetAttribute(k_final_mma, cudaFuncAttributeMaxDynamicSharedMemorySize, 143952);

    void *p0, *p1;
    cudaGetSymbolAddress(&p0, g_h0);
    cudaGetSymbolAddress(&p1, g_h1);
    float* hb[2] = {(float*)p0, (float*)p1};

    k_twiddle<<<32, 256>>>();
    k_prep2<<<32, 256>>>(fc1w);
    k_prep3<<<64, 256>>>();
    k_wbprep<<<NLAY * 4096 / 256, 256>>>(pww);
    k_wt<<<(NLAY * 512 * WID * WID) / 256, 256>>>(w1r, w1i, w2r, w2i);
    k_fc0<<<NPIX / 256, 256>>>(x, fc0w, fc0b);

    for (int l = 0; l < NLAY; l++) {
        const float* hi = hb[l & 1];
        float*       ho = hb[(l + 1) & 1];
        k_dftw_mma<<<1024, 256, 98304>>>(hi);
        k_dfth_mma<<<1024, 256, 98304>>>();
        k_mix<<<512, 256>>>(l);
        k_idfth_mma<<<1024, 256, 73728>>>();
        k_fused_mma<<<4096, 256, 123136>>>(hi, ho, l, pwb + (size_t)l * WID,
                                           (l < NLAY - 1) ? 1 : 0);
    }
    k_final_mma<<<4096, 512, 143952>>>(hb[0], out, fc1b, fc2w, fc2b);
}

// round 15
// speedup vs baseline: 1.4383x; 1.4383x over previous
#include <cuda_runtime.h>
#include <cuda_bf16.h>
#include <math.h>
#include <stdint.h>

#define BB 16
#define CIN 20
#define HH 256
#define WW 256
#define WID 64
#define M1V 16
#define M2V 16
#define NLAY 4
#define FCH 128
#define CO 20
#define HW 65536
#define NPIX (BB*HW)

#define TWO_PI 6.28318530717958647692f

typedef unsigned long long ull;

// ---------------- scratch (device globals; no allocations allowed) ----------------
__device__ float  g_h0[(size_t)BB*WID*HW];            // 268 MB ping
__device__ float  g_h1[(size_t)BB*WID*HW];            // 268 MB pong
__device__ float2 g_Fw[(size_t)BB*WID*HH*M2V];        // (b,c,h,ky)  33.5 MB
__device__ float2 g_Fm[(size_t)BB*WID*32*M2V];        // (b,c,kxi,ky) 4 MB
__device__ float2 g_Gm[(size_t)BB*WID*32*M2V];        // 4 MB
__device__ float2 g_Gw[(size_t)BB*WID*HH*M2V];        // (b,c,h,ky)  33.5 MB
__device__ float2 g_Wt[(size_t)NLAY*512*WID*WID];     // (l,m,i,o)   67 MB
__device__ float2 g_Tfh[32*HH];                       // e^{-2pi i kx h/256}
__device__ float2 g_Tih[32*HH];                       // conj
// bf16 prepped tables (pre-swizzled byte layouts)
__device__ __align__(16) unsigned char g_TsbH[16384]; // synth T hi: [px][32k] SW64
__device__ __align__(16) unsigned char g_TsbL[16384]; // synth T lo
__device__ __align__(16) unsigned char g_WbH[NLAY*8192]; // conv W hi: [och][64ch] SW128
__device__ __align__(16) unsigned char g_WbL[NLAY*8192];
__device__ __align__(16) unsigned char g_W1bH[16384]; // fc1 W hi: [128j][64ch] SW128
__device__ __align__(16) unsigned char g_W1bL[16384];
__device__ __align__(16) unsigned char g_TwbH[16384]; // dftw T hi: [kt][32n][64w] SW128
__device__ __align__(16) unsigned char g_TwbL[16384];

// ---- packed f32x2 helpers ----
__device__ __forceinline__ ull ff2(ull a, ull b, ull c) {
    ull d; asm("fma.rn.f32x2 %0,%1,%2,%3;" : "=l"(d) : "l"(a), "l"(b), "l"(c)); return d;
}
__device__ __forceinline__ ull pk(float x, float y) {
    ull d; asm("mov.b64 %0,{%1,%2};" : "=l"(d) : "f"(x), "f"(y)); return d;
}
__device__ __forceinline__ float2 upk(ull u) {
    float2 f; asm("mov.b64 {%0,%1},%2;" : "=f"(f.x), "=f"(f.y) : "l"(u)); return f;
}

// ---- fast erf-based gelu ----
__device__ __forceinline__ float gelu_fast(float v) {
    float z  = 0.70710678118654752440f * v;
    float az = fabsf(z);
    float t  = __fdividef(1.0f, fmaf(0.3275911f, az, 1.0f));
    float e  = __expf(-az * az);
    float p  = t * (0.254829592f + t * (-0.284496736f + t * (1.421413741f +
               t * (-1.453152027f + t * 1.061405429f))));
    float er = fmaf(-p, e, 1.0f);
    er = copysignf(er, z);
    return 0.5f * v * (1.0f + er);
}

#define SW128(x) ((x) ^ (((x) >> 3) & 0x70))
#define SW64(x)  ((x) ^ (((x) >> 3) & 0x30))

__device__ __forceinline__ uint32_t smem_u32(const void* p) {
    uint32_t a;
    asm("{ .reg .u64 t; cvta.to.shared.u64 t, %1; cvt.u32.u64 %0, t; }" : "=r"(a) : "l"(p));
    return a;
}
__device__ __forceinline__ void ldsm4(uint32_t& r0, uint32_t& r1, uint32_t& r2, uint32_t& r3,
                                      uint32_t a) {
    asm volatile("ldmatrix.sync.aligned.m8n8.x4.shared.b16 {%0,%1,%2,%3}, [%4];"
                 : "=r"(r0), "=r"(r1), "=r"(r2), "=r"(r3) : "r"(a));
}
__device__ __forceinline__ void mma16816(float* c, const uint32_t* a, const uint32_t* b) {
    asm volatile(
        "mma.sync.aligned.m16n8k16.row.col.f32.bf16.bf16.f32 "
        "{%0,%1,%2,%3}, {%4,%5,%6,%7}, {%8,%9}, {%0,%1,%2,%3};"
        : "+f"(c[0]), "+f"(c[1]), "+f"(c[2]), "+f"(c[3])
        : "r"(a[0]), "r"(a[1]), "r"(a[2]), "r"(a[3]), "r"(b[0]), "r"(b[1]));
}
// split fp32 pair -> bf16x2 hi pair + lo pair
__device__ __forceinline__ void split2(float xa, float xb, uint32_t& hp, uint32_t& lp) {
    asm("cvt.rn.bf16x2.f32 %0, %1, %2;" : "=r"(hp) : "f"(xb), "f"(xa));
    float ha = __uint_as_float(hp << 16);
    float hb = __uint_as_float(hp & 0xFFFF0000u);
    float la = xa - ha, lb = xb - hb;
    asm("cvt.rn.bf16x2.f32 %0, %1, %2;" : "=r"(lp) : "f"(lb), "f"(la));
}
__device__ __forceinline__ void split1(float v, __nv_bfloat16& hi, __nv_bfloat16& lo) {
    hi = __float2bfloat16_rn(v);
    lo = __float2bfloat16_rn(v - __bfloat162float(hi));
}

// ---------------- twiddle init ----------------
__global__ void k_twiddle() {
    int idx = blockIdx.x * blockDim.x + threadIdx.x;   // 8192 threads
    if (idx < 32 * HH) {
        int kxi = idx >> 8, h = idx & 255;
        int kx = (kxi < 16) ? kxi : (224 + kxi);
        int ph = (kx * h) & 255;
        float s, c;
        sincosf(-TWO_PI * (float)ph * (1.0f / 256.0f), &s, &c);
        g_Tfh[idx] = make_float2(c, s);
        g_Tih[idx] = make_float2(c, -s);
    }
    if (idx < 8192) {
        int px = idx >> 5, k = idx & 31;
        int ky = k & 15;
        int ph = (ky * px) & 255;
        float s, c;
        sincosf(TWO_PI * (float)ph * (1.0f / 256.0f), &s, &c);
        float val = ((k < 16) ? c : s) * (1.0f / 65536.0f);
        __nv_bfloat16 hi, lo; split1(val, hi, lo);
        uint32_t off = SW64((uint32_t)(px * 64 + k * 2));
        *(__nv_bfloat16*)(g_TsbH + off) = hi;
        *(__nv_bfloat16*)(g_TsbL + off) = lo;
    }
}

// ---------------- prep: fc1 weight split + dftw twiddle split ----------------
__global__ void k_prep2(const float* __restrict__ w1) {
    int idx = blockIdx.x * 256 + threadIdx.x;   // 8192
    {
        int j = idx >> 6, ch = idx & 63;
        float v = w1[idx];
        __nv_bfloat16 hi, lo; split1(v, hi, lo);
        uint32_t off = SW128((uint32_t)(j * 128 + ch * 2));
        *(__nv_bfloat16*)(g_W1bH + off) = hi;
        *(__nv_bfloat16*)(g_W1bL + off) = lo;
    }
    {
        int n = idx >> 8, w = idx & 255;
        int ky = n & 15;
        int ph = (ky * w) & 255;
        float s, c;
        sincosf(-TWO_PI * (float)ph * (1.0f / 256.0f), &s, &c);
        float val = (n < 16) ? c : s;
        __nv_bfloat16 hi, lo; split1(val, hi, lo);
        uint32_t off = (uint32_t)(w >> 6) * 4096 + SW128((uint32_t)(n * 128 + (w & 63) * 2));
        *(__nv_bfloat16*)(g_TwbH + off) = hi;
        *(__nv_bfloat16*)(g_TwbL + off) = lo;
    }
}

// ---------------- conv-weight bf16 prep ----------------
__global__ void k_wbprep(const float* __restrict__ pww) {
    int tid = blockIdx.x * 256 + threadIdx.x;          // < NLAY*4096
    int l = tid >> 12, r = tid & 4095;
    int och = r >> 6, ch = r & 63;
    float w = pww[l * 4096 + och * 64 + ch];
    __nv_bfloat16 hi, lo; split1(w, hi, lo);
    uint32_t off = SW128((uint32_t)(och * 128 + ch * 2));
    *(__nv_bfloat16*)(g_WbH + l * 8192 + off) = hi;
    *(__nv_bfloat16*)(g_WbL + l * 8192 + off) = lo;
}

// ---------------- spectral-weight transpose ----------------
__global__ void k_wt(const float* __restrict__ w1r, const float* __restrict__ w1i,
                     const float* __restrict__ w2r, const float* __restrict__ w2i) {
    int tid = blockIdx.x * blockDim.x + threadIdx.x;
    if (tid >= NLAY * 512 * WID * WID) return;
    int o   = tid & 63;
    int i   = (tid >> 6) & 63;
    int m   = (tid >> 12) & 511;
    int l   = tid >> 21;
    int kxi = m >> 4;
    int ky  = m & 15;
    int kk  = (kxi & 15) * 16 + ky;
    size_t src = ((size_t)(l * 64 + i) * 64 + o) * 256 + kk;
    float r, im;
    if (kxi < 16) { r = w1r[src]; im = w1i[src]; }
    else          { r = w2r[src]; im = w2i[src]; }
    g_Wt[tid] = make_float2(r, im);
}

// ---------------- fc0 lift ----------------
__global__ void __launch_bounds__(256) k_fc0(const float* __restrict__ x,
                                             const float* __restrict__ w,
                                             const float* __restrict__ bias) {
    __shared__ ull wp[CIN * 32];
    __shared__ ull bp[32];
    int t = threadIdx.x;
    for (int k = t; k < CIN * 32; k += 256) {
        int d2 = k & 31, c = k >> 5;
        wp[c * 32 + d2] = pk(w[(2 * d2) * CIN + c], w[(2 * d2 + 1) * CIN + c]);
    }
    if (t < 32) bp[t] = pk(bias[2 * t], bias[2 * t + 1]);
    __syncthreads();
    int p  = blockIdx.x * 256 + t;
    int b  = p >> 16;
    int sp = p & 65535;
    ull xx[CIN];
#pragma unroll
    for (int c = 0; c < CIN; c++) {
        float v = x[((size_t)(b * CIN + c) << 16) + sp];
        xx[c] = pk(v, v);
    }
#pragma unroll
    for (int d2 = 0; d2 < 32; d2++) {
        ull a = bp[d2];
#pragma unroll
        for (int c = 0; c < CIN; c++) a = ff2(xx[c], wp[c * 32 + d2], a);
        float2 f = upk(a);
        g_h0[((size_t)(b * WID + 2 * d2) << 16) + sp]     = f.x;
        g_h0[((size_t)(b * WID + 2 * d2 + 1) << 16) + sp] = f.y;
    }
}

// ============ k_dftw_mma (R13, verified) ============
__global__ void __launch_bounds__(256)
k_dftw_mma(const float* __restrict__ hin) {
    extern __shared__ char smx[];
    const uint32_t sb = smem_u32(smx);
    int t = threadIdx.x;
    size_t rbase = (size_t)blockIdx.x * 256;

    {
        const ulonglong2* srcH = (const ulonglong2*)g_TwbH;
        const ulonglong2* srcL = (const ulonglong2*)g_TwbL;
        ulonglong2* dstH = (ulonglong2*)(smx + 65536);
        ulonglong2* dstL = (ulonglong2*)(smx + 81920);
        for (int k = t; k < 1024; k += 256) { dstH[k] = srcH[k]; dstL[k] = srcL[k]; }
    }

    const int lane = t & 31;
    const int wrp  = t >> 5;
    const int pxb  = wrp * 32;
    const int grp = lane >> 3, rr = lane & 7;
    const int a_m = ((grp & 1) << 3) + rr;
    const int a_k = (grp >> 1) << 3;
    const int b_n = ((grp >> 1) << 3) + rr;
    const int b_k = (grp & 1) << 3;

    float acc[32];
#pragma unroll
    for (int i = 0; i < 32; i++) acc[i] = 0.0f;

    for (int kt = 0; kt < 4; kt++) {
        __syncthreads();
        for (int k = t; k < 8192; k += 256) {
            int row = k >> 5, p2 = k & 31;
            const float* xp = hin + (rbase + row) * 256 + kt * 64 + 2 * p2;
            uint32_t hp, lp;
            split2(xp[0], xp[1], hp, lp);
            uint32_t off = SW128((uint32_t)(row * 128 + p2 * 4));
            *(uint32_t*)(smx + off)         = hp;
            *(uint32_t*)(smx + 32768 + off) = lp;
        }
        __syncthreads();
#pragma unroll
        for (int kc = 0; kc < 4; kc++) {
            int kb = kc * 16;
            uint32_t ah[2][4], al[2][4];
#pragma unroll
            for (int mt = 0; mt < 2; mt++) {
                uint32_t aoff = SW128((uint32_t)((pxb + mt * 16 + a_m) * 128 + (kb + a_k) * 2));
                ldsm4(ah[mt][0], ah[mt][1], ah[mt][2], ah[mt][3], sb + aoff);
                ldsm4(al[mt][0], al[mt][1], al[mt][2], al[mt][3], sb + 32768 + aoff);
            }
#pragma unroll
            for (int jp = 0; jp < 2; jp++) {
                uint32_t bh[4], bl[4];
                uint32_t boff = (uint32_t)kt * 4096 +
                                SW128((uint32_t)((jp * 16 + b_n) * 128 + (kb + b_k) * 2));
                ldsm4(bh[0], bh[1], bh[2], bh[3], sb + 65536 + boff);
                ldsm4(bl[0], bl[1], bl[2], bl[3], sb + 81920 + boff);
#pragma unroll
                for (int mt = 0; mt < 2; mt++) {
#pragma unroll
                    for (int ntl = 0; ntl < 2; ntl++) {
                        float* c = &acc[(mt * 4 + jp * 2 + ntl) * 4];
                        mma16816(c, ah[mt], &bh[ntl * 2]);
                        mma16816(c, ah[mt], &bl[ntl * 2]);
                        mma16816(c, al[mt], &bh[ntl * 2]);
                    }
                }
            }
        }
    }

    int g = lane >> 2, tq = lane & 3;
#pragma unroll
    for (int mt = 0; mt < 2; mt++) {
#pragma unroll
        for (int n8 = 0; n8 < 2; n8++) {
#pragma unroll
            for (int c = 0; c < 4; c++) {
                int row = pxb + mt * 16 + g + ((c >> 1) << 3);
                int ky  = n8 * 8 + tq * 2 + (c & 1);
                float re = acc[(mt * 4 + n8) * 4 + c];
                float im = acc[(mt * 4 + n8 + 2) * 4 + c];
                g_Fw[(rbase + row) * 16 + ky] = make_float2(re, im);
            }
        }
    }
}

// ---------------- forward DFT along h (R5 FFMA) ----------------
__global__ void k_dfth() {
    extern __shared__ float2 sh[];
    float2* Fsh = sh;
    float2* Tsh = sh + 4096;
    int t = threadIdx.x;
    int bc = blockIdx.x;
    for (int k = t; k < 4096; k += 256) Fsh[k] = g_Fw[(size_t)bc * 4096 + k];
    for (int k = t; k < 8192; k += 256) Tsh[k] = g_Tfh[k];
    __syncthreads();
#pragma unroll
    for (int mm = 0; mm < 2; mm++) {
        int m = t + mm * 256;
        int kxi = m >> 4, ky = m & 15;
        float sr = 0.f, si = 0.f;
        for (int h = 0; h < 256; h++) {
            float2 f  = Fsh[h * 16 + ky];
            float2 tw = Tsh[kxi * 256 + h];
            sr = fmaf(f.x, tw.x, fmaf(-f.y, tw.y, sr));
            si = fmaf(f.x, tw.y, fmaf( f.y, tw.x, si));
        }
        g_Fm[(size_t)bc * 512 + m] = make_float2(sr, si);
    }
}

// ---------------- channel mixing (R5) ----------------
__global__ void k_mix(int layer) {
    __shared__ float2 Wm[WID * WID];
    __shared__ float2 Fsh[BB * WID];
    int t = threadIdx.x;
    int m = blockIdx.x;
    const float2* wsrc = g_Wt + ((size_t)layer * 512 + m) * 4096;
    for (int k = t; k < 4096; k += 256) Wm[k] = wsrc[k];
    for (int k = t; k < 1024; k += 256) {
        int b = k >> 6, i = k & 63;
        Fsh[k] = g_Fm[(size_t)(b * 64 + i) * 512 + m];
    }
    __syncthreads();
#pragma unroll
    for (int u = 0; u < 4; u++) {
        int outi = t + u * 256;
        int b = outi >> 6, o = outi & 63;
        float sr = 0.f, si = 0.f;
#pragma unroll 8
        for (int i = 0; i < 64; i++) {
            float2 f = Fsh[b * 64 + i];
            float2 w = Wm[i * 64 + o];
            sr = fmaf(f.x, w.x, fmaf(-f.y, w.y, sr));
            si = fmaf(f.x, w.y, fmaf( f.y, w.x, si));
        }
        g_Gm[(size_t)(b * 64 + o) * 512 + m] = make_float2(sr, si);
    }
}

// ---------------- inverse transform along h (R5 FFMA) ----------------
__global__ void k_idfth() {
    extern __shared__ char shb[];
    ulonglong2* Gsh2 = (ulonglong2*)shb;
    float2*     Tsh  = (float2*)(shb + 8192);
    int t = threadIdx.x;
    int bc = blockIdx.x;
    for (int k = t; k < 512; k += 256) {
        float2 g = g_Gm[(size_t)bc * 512 + k];
        ulonglong2 d; d.x = pk(g.x, g.x); d.y = pk(g.y, g.y);
        Gsh2[k] = d;
    }
    for (int k = t; k < 8192; k += 256) Tsh[k] = g_Tih[k];
    __syncthreads();
    int h = t;
    ull acc[16];
#pragma unroll
    for (int k = 0; k < 16; k++) acc[k] = 0ULL;
    for (int kxi = 0; kxi < 32; kxi++) {
        float2 tw = Tsh[kxi * 256 + h];
        ull t1 = pk(tw.x, tw.y);
        ull t2 = pk(-tw.y, tw.x);
        const ulonglong2* gp = &Gsh2[kxi * 16];
#pragma unroll
        for (int ky = 0; ky < 16; ky++) {
            ulonglong2 g = gp[ky];
            acc[ky] = ff2(g.x, t1, acc[ky]);
            acc[ky] = ff2(g.y, t2, acc[ky]);
        }
    }
    ull* outp = (ull*)(g_Gw + ((size_t)bc * 256 + h) * 16);
#pragma unroll
    for (int ky = 0; ky < 16; ky++) outp[ky] = acc[ky];
}

// ============ k_fused_mma v2: two-phase smem reuse, 82KB -> 2 blocks/SM ============
// Phase A (synthesis K=32): TH 0..16384 | TL 16384..32768 | GH 32768..36864 |
//   GL 36864..40960. Phase B (conv K=64): XH 0..32768 | XL 32768..65536 |
//   WH 65536..73728 | WL 73728..81920. bias at 81920 (256B). total 82176.
//   epilogue stage [64][260] floats overlaps 0..66560.
__global__ void __launch_bounds__(256)
k_fused_mma(const float* __restrict__ hin, float* __restrict__ hout,
            int layer, const float* __restrict__ pwb, int dogelu) {
    extern __shared__ char smx[];
    const uint32_t sb = smem_u32(smx);
    int t = threadIdx.x;
    int b = blockIdx.x >> 8, row = blockIdx.x & 255;

    const int lane = t & 31;
    const int wrp  = t >> 5;
    const int pxb  = wrp * 32;
    const int grp = lane >> 3, rr = lane & 7;
    const int a_m = ((grp & 1) << 3) + rr;
    const int a_k = (grp >> 1) << 3;
    const int b_n = ((grp >> 1) << 3) + rr;
    const int b_k = (grp & 1) << 3;

    float acc[2][8][4];
#pragma unroll
    for (int mt = 0; mt < 2; mt++)
#pragma unroll
        for (int n8 = 0; n8 < 8; n8++)
#pragma unroll
            for (int c = 0; c < 4; c++) acc[mt][n8][c] = 0.0f;

    // ---- Phase A staging: synth T tiles + Gd + bias ----
    {
        const ulonglong2* srcH = (const ulonglong2*)g_TsbH;
        const ulonglong2* srcL = (const ulonglong2*)g_TsbL;
        ulonglong2* dstH = (ulonglong2*)smx;
        ulonglong2* dstL = (ulonglong2*)(smx + 16384);
        for (int k = t; k < 1024; k += 256) { dstH[k] = srcH[k]; dstL[k] = srcL[k]; }
    }
    for (int k = t; k < 1024; k += 256) {
        int och = k >> 4, ky = k & 15;
        float2 g = g_Gw[(((size_t)(b * 64 + och)) * 256 + row) * 16 + ky];
        float vx = (ky == 0) ? g.x : 2.0f * g.x;
        float vy = (ky == 0) ? 0.0f : -2.0f * g.y;
        __nv_bfloat16 hx, lx, hy, ly;
        split1(vx, hx, lx);
        split1(vy, hy, ly);
        uint32_t off1 = SW64((uint32_t)(och * 64 + ky * 2));
        uint32_t off2 = SW64((uint32_t)(och * 64 + (16 + ky) * 2));
        *(__nv_bfloat16*)(smx + 32768 + off1) = hx;
        *(__nv_bfloat16*)(smx + 36864 + off1) = lx;
        *(__nv_bfloat16*)(smx + 32768 + off2) = hy;
        *(__nv_bfloat16*)(smx + 36864 + off2) = ly;
    }
    if (t < 64) ((float*)(smx + 81920))[t] = pwb[t];
    __syncthreads();

    // ---- Phase A MMAs: synthesis, K=32, SW64 tiles ----
#pragma unroll
    for (int kt = 0; kt < 2; kt++) {
        int kb = kt * 16;
        uint32_t ah[2][4], al[2][4];
#pragma unroll
        for (int mt = 0; mt < 2; mt++) {
            uint32_t aoff = SW64((uint32_t)((pxb + mt * 16 + a_m) * 64 + (kb + a_k) * 2));
            ldsm4(ah[mt][0], ah[mt][1], ah[mt][2], ah[mt][3], sb + aoff);
            ldsm4(al[mt][0], al[mt][1], al[mt][2], al[mt][3], sb + 16384 + aoff);
        }
#pragma unroll
        for (int jp = 0; jp < 4; jp++) {
            int nb = jp * 16;
            uint32_t bh[4], bl[4];
            uint32_t boff = SW64((uint32_t)((nb + b_n) * 64 + (kb + b_k) * 2));
            ldsm4(bh[0], bh[1], bh[2], bh[3], sb + 32768 + boff);
            ldsm4(bl[0], bl[1], bl[2], bl[3], sb + 36864 + boff);
#pragma unroll
            for (int mt = 0; mt < 2; mt++) {
#pragma unroll
                for (int ntl = 0; ntl < 2; ntl++) {
                    float* c = acc[mt][jp * 2 + ntl];
                    mma16816(c, ah[mt], &bh[ntl * 2]);
                    mma16816(c, ah[mt], &bl[ntl * 2]);
                    mma16816(c, al[mt], &bh[ntl * 2]);
                }
            }
        }
    }
    __syncthreads();   // done reading phase-A smem

    // ---- Phase B staging: X hi/lo + W hi/lo ----
    {
        const float* xp = hin + ((size_t)(b * 64) << 16) + row * 256 + t;
#pragma unroll
        for (int i2 = 0; i2 < 32; i2++) {
            float xa = xp[(size_t)(2 * i2) << 16];
            float xb = xp[(size_t)(2 * i2 + 1) << 16];
            uint32_t hp, lp;
            split2(xa, xb, hp, lp);
            uint32_t off = SW128((uint32_t)(t * 128 + i2 * 4));
            *(uint32_t*)(smx + off)         = hp;
            *(uint32_t*)(smx + 32768 + off) = lp;
        }
    }
    {
        const ulonglong2* srcH = (const ulonglong2*)(g_WbH + layer * 8192);
        const ulonglong2* srcL = (const ulonglong2*)(g_WbL + layer * 8192);
        ulonglong2* dstH = (ulonglong2*)(smx + 65536);
        ulonglong2* dstL = (ulonglong2*)(smx + 73728);
        for (int k = t; k < 512; k += 256) { dstH[k] = srcH[k]; dstL[k] = srcL[k]; }
    }
    __syncthreads();

    // ---- Phase B MMAs: conv, K=64, SW128 tiles ----
#pragma unroll
    for (int kt = 0; kt < 4; kt++) {
        int kb = kt * 16;
        uint32_t ah[2][4], al[2][4];
#pragma unroll
        for (int mt = 0; mt < 2; mt++) {
            uint32_t aoff = SW128((uint32_t)((pxb + mt * 16 + a_m) * 128 + (kb + a_k) * 2));
            ldsm4(ah[mt][0], ah[mt][1], ah[mt][2], ah[mt][3], sb + aoff);
            ldsm4(al[mt][0], al[mt][1], al[mt][2], al[mt][3], sb + 32768 + aoff);
        }
#pragma unroll
        for (int jp = 0; jp < 4; jp++) {
            int nb = jp * 16;
            uint32_t bh[4], bl[4];
            uint32_t boff = SW128((uint32_t)((nb + b_n) * 128 + (kb + b_k) * 2));
            ldsm4(bh[0], bh[1], bh[2], bh[3], sb + 65536 + boff);
            ldsm4(bl[0], bl[1], bl[2], bl[3], sb + 73728 + boff);
#pragma unroll
            for (int mt = 0; mt < 2; mt++) {
#pragma unroll
                for (int ntl = 0; ntl < 2; ntl++) {
                    float* c = acc[mt][jp * 2 + ntl];
                    mma16816(c, ah[mt], &bh[ntl * 2]);
                    mma16816(c, ah[mt], &bl[ntl * 2]);
                    mma16816(c, al[mt], &bh[ntl * 2]);
                }
            }
        }
    }

    // ---- epilogue ----
    __syncthreads();
    {
        float* stage = (float*)smx;
        const float* bsh = (const float*)(smx + 81920);
        int g = lane >> 2, tq = lane & 3;
#pragma unroll
        for (int mt = 0; mt < 2; mt++) {
            int px0 = pxb + mt * 16 + g;
#pragma unroll
            for (int n8 = 0; n8 < 8; n8++) {
                int och = n8 * 8 + tq * 2;
                float b0 = bsh[och], b1 = bsh[och + 1];
                float v00 = acc[mt][n8][0] + b0;
                float v01 = acc[mt][n8][1] + b1;
                float v10 = acc[mt][n8][2] + b0;
                float v11 = acc[mt][n8][3] + b1;
                if (dogelu) {
                    v00 = gelu_fast(v00); v01 = gelu_fast(v01);
                    v10 = gelu_fast(v10); v11 = gelu_fast(v11);
                }
                stage[och * 260 + px0]           = v00;
                stage[(och + 1) * 260 + px0]     = v01;
                stage[och * 260 + px0 + 8]       = v10;
                stage[(och + 1) * 260 + px0 + 8] = v11;
            }
        }
    }
    __syncthreads();
    {
        const float* stage = (const float*)smx;
        float* outp = hout + ((size_t)(b * 64) << 16) + row * 256 + t;
#pragma unroll 8
        for (int i = 0; i < 64; i++)
            outp[(size_t)i << 16] = stage[i * 260 + t];
    }
}

// ============ k_final_mma (R13, verified) ============
__global__ void __launch_bounds__(512)
k_final_mma(const float* __restrict__ hin, float* __restrict__ out,
            const float* __restrict__ b1, const float* __restrict__ w2,
            const float* __restrict__ b2) {
    extern __shared__ char smx[];
    const uint32_t sb = smem_u32(smx);
    int t = threadIdx.x;
    int b = blockIdx.x >> 8, row = blockIdx.x & 255;

    size_t base = ((size_t)(b * 64) << 16) + (size_t)row * 256;
    for (int k = t; k < 8192; k += 512) {
        int px = k & 255, i2 = k >> 8;
        float xa = hin[base + ((size_t)(2 * i2) << 16) + px];
        float xb = hin[base + ((size_t)(2 * i2 + 1) << 16) + px];
        uint32_t hp, lp;
        split2(xa, xb, hp, lp);
        uint32_t off = SW128((uint32_t)(px * 128 + i2 * 4));
        *(uint32_t*)(smx + off)         = hp;
        *(uint32_t*)(smx + 32768 + off) = lp;
    }
    {
        const ulonglong2* srcH = (const ulonglong2*)g_W1bH;
        const ulonglong2* srcL = (const ulonglong2*)g_W1bL;
        ulonglong2* dstH = (ulonglong2*)(smx + 65536);
        ulonglong2* dstL = (ulonglong2*)(smx + 81920);
        for (int k = t; k < 1024; k += 512) { dstH[k] = srcH[k]; dstL[k] = srcL[k]; }
    }
    {
        ull* w2t = (ull*)(smx + 133120);
        for (int k = t; k < FCH * 10; k += 512) {
            int o2 = k >> 7, j = k & 127;
            w2t[j * 10 + o2] = pk(w2[(2 * o2) * FCH + j], w2[(2 * o2 + 1) * FCH + j]);
        }
    }
    if (t < FCH) ((float*)(smx + 143360))[t] = b1[t];
    if (t < 10)  ((ull*)(smx + 143872))[t] = pk(b2[2 * t], b2[2 * t + 1]);
    __syncthreads();

    const int lane = t & 31;
    const int wrp  = t >> 5;
    const int pxb  = wrp * 16;
    const int grp = lane >> 3, rr = lane & 7;
    const int a_m = ((grp & 1) << 3) + rr;
    const int a_k = (grp >> 1) << 3;
    const int b_n = ((grp >> 1) << 3) + rr;
    const int b_k = (grp & 1) << 3;

    float acc[64];
#pragma unroll
    for (int i = 0; i < 64; i++) acc[i] = 0.0f;

#pragma unroll
    for (int kt = 0; kt < 4; kt++) {
        int kb = kt * 16;
        uint32_t ah[4], al[4];
        uint32_t aoff = SW128((uint32_t)((pxb + a_m) * 128 + (kb + a_k) * 2));
        ldsm4(ah[0], ah[1], ah[2], ah[3], sb + aoff);
        ldsm4(al[0], al[1], al[2], al[3], sb + 32768 + aoff);
#pragma unroll
        for (int jp = 0; jp < 8; jp++) {
            uint32_t bh[4], bl[4];
            uint32_t boff = SW128((uint32_t)((jp * 16 + b_n) * 128 + (kb + b_k) * 2));
            ldsm4(bh[0], bh[1], bh[2], bh[3], sb + 65536 + boff);
            ldsm4(bl[0], bl[1], bl[2], bl[3], sb + 81920 + boff);
#pragma unroll
            for (int ntl = 0; ntl < 2; ntl++) {
                float* c = &acc[(jp * 2 + ntl) * 4];
                mma16816(c, ah, &bh[ntl * 2]);
                mma16816(c, ah, &bl[ntl * 2]);
                mma16816(c, al, &bh[ntl * 2]);
            }
        }
    }

    __syncthreads();
    {
        float* stage = (float*)smx;
        const float* b1sh = (const float*)(smx + 143360);
        int g = lane >> 2, tq = lane & 3;
        int px0 = pxb + g;
#pragma unroll
        for (int n8 = 0; n8 < 16; n8++) {
            int j0 = n8 * 8 + tq * 2;
            float bb0 = b1sh[j0], bb1 = b1sh[j0 + 1];
            stage[j0 * 260 + px0]           = gelu_fast(acc[n8 * 4 + 0] + bb0);
            stage[(j0 + 1) * 260 + px0]     = gelu_fast(acc[n8 * 4 + 1] + bb1);
            stage[j0 * 260 + px0 + 8]       = gelu_fast(acc[n8 * 4 + 2] + bb0);
            stage[(j0 + 1) * 260 + px0 + 8] = gelu_fast(acc[n8 * 4 + 3] + bb1);
        }
    }
    __syncthreads();
    {
        const float* stage = (const float*)smx;
        const ull* w2t = (const ull*)(smx + 133120);
        const ull* b2p = (const ull*)(smx + 143872);
        int px = t & 255;
        int oh = t >> 8;
        ull a5[5];
#pragma unroll
        for (int k = 0; k < 5; k++) a5[k] = b2p[oh * 5 + k];
        for (int j = 0; j < FCH; j++) {
            float hv = stage[j * 260 + px];
            ull hh = pk(hv, hv);
            const ull* wp = &w2t[j * 10 + oh * 5];
#pragma unroll
            for (int k = 0; k < 5; k++) a5[k] = ff2(hh, wp[k], a5[k]);
        }
        size_t sp = (size_t)row * 256 + px;
#pragma unroll
        for (int k = 0; k < 5; k++) {
            int o2 = oh * 5 + k;
            float2 a = upk(a5[k]);
            out[((size_t)(b * CO + 2 * o2) << 16) + sp]     = a.x;
            out[((size_t)(b * CO + 2 * o2 + 1) << 16) + sp] = a.y;
        }
    }
}

// ---------------- orchestration ----------------
extern "C" void kernel_launch(void* const* d_in, const int* in_sizes, int n_in,
                              void* d_out, int out_size) {
    const float* x    = (const float*)d_in[0];
    const float* w1r  = (const float*)d_in[1];
    const float* w1i  = (const float*)d_in[2];
    const float* w2r  = (const float*)d_in[3];
    const float* w2i  = (const float*)d_in[4];
    const float* pww  = (const float*)d_in[5];
    const float* pwb  = (const float*)d_in[6];
    const float* fc0w = (const float*)d_in[7];
    const float* fc0b = (const float*)d_in[8];
    const float* fc1w = (const float*)d_in[9];
    const float* fc1b = (const float*)d_in[10];
    const float* fc2w = (const float*)d_in[11];
    const float* fc2b = (const float*)d_in[12];
    float* out = (float*)d_out;

    cudaFuncSetAttribute(k_dftw_mma,  cudaFuncAttributeMaxDynamicSharedMemorySize, 98304);
    cudaFuncSetAttribute(k_dfth,      cudaFuncAttributeMaxDynamicSharedMemorySize, 98304);
    cudaFuncSetAttribute(k_idfth,     cudaFuncAttributeMaxDynamicSharedMemorySize, 73728);
    cudaFuncSetAttribute(k_fused_mma, cudaFuncAttributeMaxDynamicSharedMemorySize, 82176);
    cudaFuncSetAttribute(k_final_mma, cudaFuncAttributeMaxDynamicSharedMemorySize, 143952);

    void *p0, *p1;
    cudaGetSymbolAddress(&p0, g_h0);
    cudaGetSymbolAddress(&p1, g_h1);
    float* hb[2] = {(float*)p0, (float*)p1};

    k_twiddle<<<32, 256>>>();
    k_prep2<<<32, 256>>>(fc1w);
    k_wbprep<<<NLAY * 4096 / 256, 256>>>(pww);
    k_wt<<<(NLAY * 512 * WID * WID) / 256, 256>>>(w1r, w1i, w2r, w2i);
    k_fc0<<<NPIX / 256, 256>>>(x, fc0w, fc0b);

    for (int l = 0; l < NLAY; l++) {
        const float* hi = hb[l & 1];
        float*       ho = hb[(l + 1) & 1];
        k_dftw_mma<<<1024, 256, 98304>>>(hi);
        k_dfth<<<1024, 256, 98304>>>();
        k_mix<<<512, 256>>>(l);
        k_idfth<<<1024, 256, 73728>>>();
        k_fused_mma<<<4096, 256, 82176>>>(hi, ho, l, pwb + (size_t)l * WID,
                                          (l < NLAY - 1) ? 1 : 0);
    }
    k_final_mma<<<4096, 512, 143952>>>(hb[0], out, fc1b, fc2w, fc2b);
}

// round 16
// speedup vs baseline: 1.6591x; 1.1535x over previous
#include <cuda_runtime.h>
#include <cuda_bf16.h>
#include <math.h>
#include <stdint.h>

#define BB 16
#define CIN 20
#define HH 256
#define WW 256
#define WID 64
#define M1V 16
#define M2V 16
#define NLAY 4
#define FCH 128
#define CO 20
#define HW 65536
#define NPIX (BB*HW)

#define TWO_PI 6.28318530717958647692f

typedef unsigned long long ull;

// ---------------- scratch (device globals; no allocations allowed) ----------------
__device__ float  g_h0[(size_t)BB*WID*HW];            // 268 MB ping
__device__ float  g_h1[(size_t)BB*WID*HW];            // 268 MB pong
__device__ float2 g_Fm[(size_t)BB*WID*32*M2V];        // (b,c,kxi,ky) 4 MB
__device__ float2 g_Gm[(size_t)BB*WID*32*M2V];        // 4 MB
__device__ float2 g_Gw[(size_t)BB*WID*HH*M2V];        // (b,c,h,ky)  33.5 MB
__device__ float2 g_Wt[(size_t)NLAY*512*WID*WID];     // (l,m,i,o)   67 MB
// Fw in bf16 hi/lo, dfth B layout: [bc][kt(h>>6)][32n][64h] SW128 (n<16 Fr, n>=16 Fi)
__device__ __align__(16) unsigned char g_FwBH[(size_t)1024*16384]; // 16 MB
__device__ __align__(16) unsigned char g_FwBL[(size_t)1024*16384]; // 16 MB
// bf16 prepped tables (pre-swizzled byte layouts)
__device__ __align__(16) unsigned char g_TsbH[16384]; // synth T hi: [px][32k] SW64
__device__ __align__(16) unsigned char g_TsbL[16384]; // synth T lo
__device__ __align__(16) unsigned char g_WbH[NLAY*8192]; // conv W hi: [och][64ch] SW128
__device__ __align__(16) unsigned char g_WbL[NLAY*8192];
__device__ __align__(16) unsigned char g_W1bH[16384]; // fc1 W hi: [128j][64ch] SW128
__device__ __align__(16) unsigned char g_W1bL[16384];
__device__ __align__(16) unsigned char g_TwbH[16384]; // dftw T hi: [kt][32n][64w] SW128
__device__ __align__(16) unsigned char g_TwbL[16384];
__device__ __align__(16) unsigned char g_ThfH[32768]; // dfth A: [kt][64m][64h] SW128 (m<32 cos, m>=32 -sin)
__device__ __align__(16) unsigned char g_ThfL[32768];
__device__ __align__(16) unsigned char g_TihH[32768]; // idfth A: [256h][64k] SW128 (k<32 cos, k>=32 +sin)
__device__ __align__(16) unsigned char g_TihL[32768];

// ---- packed f32x2 helpers ----
__device__ __forceinline__ ull ff2(ull a, ull b, ull c) {
    ull d; asm("fma.rn.f32x2 %0,%1,%2,%3;" : "=l"(d) : "l"(a), "l"(b), "l"(c)); return d;
}
__device__ __forceinline__ ull pk(float x, float y) {
    ull d; asm("mov.b64 %0,{%1,%2};" : "=l"(d) : "f"(x), "f"(y)); return d;
}
__device__ __forceinline__ float2 upk(ull u) {
    float2 f; asm("mov.b64 {%0,%1},%2;" : "=f"(f.x), "=f"(f.y) : "l"(u)); return f;
}

// ---- fast erf-based gelu ----
__device__ __forceinline__ float gelu_fast(float v) {
    float z  = 0.70710678118654752440f * v;
    float az = fabsf(z);
    float t  = __fdividef(1.0f, fmaf(0.3275911f, az, 1.0f));
    float e  = __expf(-az * az);
    float p  = t * (0.254829592f + t * (-0.284496736f + t * (1.421413741f +
               t * (-1.453152027f + t * 1.061405429f))));
    float er = fmaf(-p, e, 1.0f);
    er = copysignf(er, z);
    return 0.5f * v * (1.0f + er);
}

#define SW128(x) ((x) ^ (((x) >> 3) & 0x70))
#define SW64(x)  ((x) ^ (((x) >> 3) & 0x30))

__device__ __forceinline__ uint32_t smem_u32(const void* p) {
    uint32_t a;
    asm("{ .reg .u64 t; cvta.to.shared.u64 t, %1; cvt.u32.u64 %0, t; }" : "=r"(a) : "l"(p));
    return a;
}
__device__ __forceinline__ void ldsm4(uint32_t& r0, uint32_t& r1, uint32_t& r2, uint32_t& r3,
                                      uint32_t a) {
    asm volatile("ldmatrix.sync.aligned.m8n8.x4.shared.b16 {%0,%1,%2,%3}, [%4];"
                 : "=r"(r0), "=r"(r1), "=r"(r2), "=r"(r3) : "r"(a));
}
__device__ __forceinline__ void mma16816(float* c, const uint32_t* a, const uint32_t* b) {
    asm volatile(
        "mma.sync.aligned.m16n8k16.row.col.f32.bf16.bf16.f32 "
        "{%0,%1,%2,%3}, {%4,%5,%6,%7}, {%8,%9}, {%0,%1,%2,%3};"
        : "+f"(c[0]), "+f"(c[1]), "+f"(c[2]), "+f"(c[3])
        : "r"(a[0]), "r"(a[1]), "r"(a[2]), "r"(a[3]), "r"(b[0]), "r"(b[1]));
}
// split fp32 pair -> bf16x2 hi pair + lo pair
__device__ __forceinline__ void split2(float xa, float xb, uint32_t& hp, uint32_t& lp) {
    asm("cvt.rn.bf16x2.f32 %0, %1, %2;" : "=r"(hp) : "f"(xb), "f"(xa));
    float ha = __uint_as_float(hp << 16);
    float hb = __uint_as_float(hp & 0xFFFF0000u);
    float la = xa - ha, lb = xb - hb;
    asm("cvt.rn.bf16x2.f32 %0, %1, %2;" : "=r"(lp) : "f"(lb), "f"(la));
}
__device__ __forceinline__ void split1(float v, __nv_bfloat16& hi, __nv_bfloat16& lo) {
    hi = __float2bfloat16_rn(v);
    lo = __float2bfloat16_rn(v - __bfloat162float(hi));
}

// ---------------- twiddle init (synthesis table) ----------------
__global__ void k_twiddle() {
    int idx = blockIdx.x * blockDim.x + threadIdx.x;   // 8192 threads
    if (idx < 8192) {
        int px = idx >> 5, k = idx & 31;
        int ky = k & 15;
        int ph = (ky * px) & 255;
        float s, c;
        sincosf(TWO_PI * (float)ph * (1.0f / 256.0f), &s, &c);
        float val = ((k < 16) ? c : s) * (1.0f / 65536.0f);
        __nv_bfloat16 hi, lo; split1(val, hi, lo);
        uint32_t off = SW64((uint32_t)(px * 64 + k * 2));
        *(__nv_bfloat16*)(g_TsbH + off) = hi;
        *(__nv_bfloat16*)(g_TsbL + off) = lo;
    }
}

// ---------------- prep: fc1 weight split + dftw twiddle split ----------------
__global__ void k_prep2(const float* __restrict__ w1) {
    int idx = blockIdx.x * 256 + threadIdx.x;   // 8192
    {
        int j = idx >> 6, ch = idx & 63;
        float v = w1[idx];
        __nv_bfloat16 hi, lo; split1(v, hi, lo);
        uint32_t off = SW128((uint32_t)(j * 128 + ch * 2));
        *(__nv_bfloat16*)(g_W1bH + off) = hi;
        *(__nv_bfloat16*)(g_W1bL + off) = lo;
    }
    {
        int n = idx >> 8, w = idx & 255;
        int ky = n & 15;
        int ph = (ky * w) & 255;
        float s, c;
        sincosf(-TWO_PI * (float)ph * (1.0f / 256.0f), &s, &c);
        float val = (n < 16) ? c : s;
        __nv_bfloat16 hi, lo; split1(val, hi, lo);
        uint32_t off = (uint32_t)(w >> 6) * 4096 + SW128((uint32_t)(n * 128 + (w & 63) * 2));
        *(__nv_bfloat16*)(g_TwbH + off) = hi;
        *(__nv_bfloat16*)(g_TwbL + off) = lo;
    }
}

// ---------------- prep: dfth / idfth twiddle A-tables ----------------
__global__ void k_prep3() {
    int idx = blockIdx.x * 256 + threadIdx.x;   // 16384
    {   // dfth A: [kt][64m][64h] SW128; m<32 -> cos, m>=32 -> -sin
        int m = idx >> 8, h = idx & 255;
        int kxi = m & 31, part = m >> 5;
        int kx = (kxi < 16) ? kxi : (224 + kxi);
        int ph = (kx * h) & 255;
        float s, c;
        sincosf(-TWO_PI * (float)ph * (1.0f / 256.0f), &s, &c);   // s = -sin
        float val = part ? s : c;
        __nv_bfloat16 hi, lo; split1(val, hi, lo);
        uint32_t off = (uint32_t)(h >> 6) * 8192 + SW128((uint32_t)(m * 128 + (h & 63) * 2));
        *(__nv_bfloat16*)(g_ThfH + off) = hi;
        *(__nv_bfloat16*)(g_ThfL + off) = lo;
    }
    {   // idfth A: [256h][64k] SW128; k<32 -> cos, k>=32 -> +sin
        int h = idx >> 6, k = idx & 63;
        int kxi = k & 31, part = k >> 5;
        int kx = (kxi < 16) ? kxi : (224 + kxi);
        int ph = (kx * h) & 255;
        float s, c;
        sincosf(TWO_PI * (float)ph * (1.0f / 256.0f), &s, &c);    // s = +sin
        float val = part ? s : c;
        __nv_bfloat16 hi, lo; split1(val, hi, lo);
        uint32_t off = SW128((uint32_t)(h * 128 + k * 2));
        *(__nv_bfloat16*)(g_TihH + off) = hi;
        *(__nv_bfloat16*)(g_TihL + off) = lo;
    }
}

// ---------------- conv-weight bf16 prep ----------------
__global__ void k_wbprep(const float* __restrict__ pww) {
    int tid = blockIdx.x * 256 + threadIdx.x;          // < NLAY*4096
    int l = tid >> 12, r = tid & 4095;
    int och = r >> 6, ch = r & 63;
    float w = pww[l * 4096 + och * 64 + ch];
    __nv_bfloat16 hi, lo; split1(w, hi, lo);
    uint32_t off = SW128((uint32_t)(och * 128 + ch * 2));
    *(__nv_bfloat16*)(g_WbH + l * 8192 + off) = hi;
    *(__nv_bfloat16*)(g_WbL + l * 8192 + off) = lo;
}

// ---------------- spectral-weight transpose ----------------
__global__ void k_wt(const float* __restrict__ w1r, const float* __restrict__ w1i,
                     const float* __restrict__ w2r, const float* __restrict__ w2i) {
    int tid = blockIdx.x * blockDim.x + threadIdx.x;
    if (tid >= NLAY * 512 * WID * WID) return;
    int o   = tid & 63;
    int i   = (tid >> 6) & 63;
    int m   = (tid >> 12) & 511;
    int l   = tid >> 21;
    int kxi = m >> 4;
    int ky  = m & 15;
    int kk  = (kxi & 15) * 16 + ky;
    size_t src = ((size_t)(l * 64 + i) * 64 + o) * 256 + kk;
    float r, im;
    if (kxi < 16) { r = w1r[src]; im = w1i[src]; }
    else          { r = w2r[src]; im = w2i[src]; }
    g_Wt[tid] = make_float2(r, im);
}

// ---------------- fc0 lift ----------------
__global__ void __launch_bounds__(256) k_fc0(const float* __restrict__ x,
                                             const float* __restrict__ w,
                                             const float* __restrict__ bias) {
    __shared__ ull wp[CIN * 32];
    __shared__ ull bp[32];
    int t = threadIdx.x;
    for (int k = t; k < CIN * 32; k += 256) {
        int d2 = k & 31, c = k >> 5;
        wp[c * 32 + d2] = pk(w[(2 * d2) * CIN + c], w[(2 * d2 + 1) * CIN + c]);
    }
    if (t < 32) bp[t] = pk(bias[2 * t], bias[2 * t + 1]);
    __syncthreads();
    int p  = blockIdx.x * 256 + t;
    int b  = p >> 16;
    int sp = p & 65535;
    ull xx[CIN];
#pragma unroll
    for (int c = 0; c < CIN; c++) {
        float v = x[((size_t)(b * CIN + c) << 16) + sp];
        xx[c] = pk(v, v);
    }
#pragma unroll
    for (int d2 = 0; d2 < 32; d2++) {
        ull a = bp[d2];
#pragma unroll
        for (int c = 0; c < CIN; c++) a = ff2(xx[c], wp[c * 32 + d2], a);
        float2 f = upk(a);
        g_h0[((size_t)(b * WID + 2 * d2) << 16) + sp]     = f.x;
        g_h0[((size_t)(b * WID + 2 * d2 + 1) << 16) + sp] = f.y;
    }
}

// ============ k_dftw_mma: writes Fw as bf16 hi/lo in dfth B-layout ============
// grid 1024 (one bc = 256 rows each), 256 threads.
__global__ void __launch_bounds__(256)
k_dftw_mma(const float* __restrict__ hin) {
    extern __shared__ char smx[];
    const uint32_t sb = smem_u32(smx);
    int t = threadIdx.x;
    int bc = blockIdx.x;
    size_t rbase = (size_t)bc * 256;

    {
        const ulonglong2* srcH = (const ulonglong2*)g_TwbH;
        const ulonglong2* srcL = (const ulonglong2*)g_TwbL;
        ulonglong2* dstH = (ulonglong2*)(smx + 65536);
        ulonglong2* dstL = (ulonglong2*)(smx + 81920);
        for (int k = t; k < 1024; k += 256) { dstH[k] = srcH[k]; dstL[k] = srcL[k]; }
    }

    const int lane = t & 31;
    const int wrp  = t >> 5;
    const int pxb  = wrp * 32;
    const int grp = lane >> 3, rr = lane & 7;
    const int a_m = ((grp & 1) << 3) + rr;
    const int a_k = (grp >> 1) << 3;
    const int b_n = ((grp >> 1) << 3) + rr;
    const int b_k = (grp & 1) << 3;

    float acc[32];
#pragma unroll
    for (int i = 0; i < 32; i++) acc[i] = 0.0f;

    for (int kt = 0; kt < 4; kt++) {
        __syncthreads();
        for (int k = t; k < 8192; k += 256) {
            int row = k >> 5, p2 = k & 31;
            const float* xp = hin + (rbase + row) * 256 + kt * 64 + 2 * p2;
            uint32_t hp, lp;
            split2(xp[0], xp[1], hp, lp);
            uint32_t off = SW128((uint32_t)(row * 128 + p2 * 4));
            *(uint32_t*)(smx + off)         = hp;
            *(uint32_t*)(smx + 32768 + off) = lp;
        }
        __syncthreads();
#pragma unroll
        for (int kc = 0; kc < 4; kc++) {
            int kb = kc * 16;
            uint32_t ah[2][4], al[2][4];
#pragma unroll
            for (int mt = 0; mt < 2; mt++) {
                uint32_t aoff = SW128((uint32_t)((pxb + mt * 16 + a_m) * 128 + (kb + a_k) * 2));
                ldsm4(ah[mt][0], ah[mt][1], ah[mt][2], ah[mt][3], sb + aoff);
                ldsm4(al[mt][0], al[mt][1], al[mt][2], al[mt][3], sb + 32768 + aoff);
            }
#pragma unroll
            for (int jp = 0; jp < 2; jp++) {
                uint32_t bh[4], bl[4];
                uint32_t boff = (uint32_t)kt * 4096 +
                                SW128((uint32_t)((jp * 16 + b_n) * 128 + (kb + b_k) * 2));
                ldsm4(bh[0], bh[1], bh[2], bh[3], sb + 65536 + boff);
                ldsm4(bl[0], bl[1], bl[2], bl[3], sb + 81920 + boff);
#pragma unroll
                for (int mt = 0; mt < 2; mt++) {
#pragma unroll
                    for (int ntl = 0; ntl < 2; ntl++) {
                        float* c = &acc[(mt * 4 + jp * 2 + ntl) * 4];
                        mma16816(c, ah[mt], &bh[ntl * 2]);
                        mma16816(c, ah[mt], &bl[ntl * 2]);
                        mma16816(c, al[mt], &bh[ntl * 2]);
                    }
                }
            }
        }
    }

    // write bf16 hi/lo Fw tiles: [bc][kt][n][hl] SW128, n<16: re, n>=16: im
    int g = lane >> 2, tq = lane & 3;
    size_t base = (size_t)bc * 16384;
#pragma unroll
    for (int mt = 0; mt < 2; mt++) {
#pragma unroll
        for (int n8 = 0; n8 < 2; n8++) {
#pragma unroll
            for (int c = 0; c < 4; c++) {
                int h  = pxb + mt * 16 + g + ((c >> 1) << 3);
                int ky = n8 * 8 + tq * 2 + (c & 1);
                float re = acc[(mt * 4 + n8) * 4 + c];
                float im = acc[(mt * 4 + n8 + 2) * 4 + c];
                int kt = h >> 6, hl = h & 63;
                size_t cb = base + (size_t)kt * 4096;
                uint32_t offR = SW128((uint32_t)(ky * 128 + hl * 2));
                uint32_t offI = SW128((uint32_t)((16 + ky) * 128 + hl * 2));
                __nv_bfloat16 hr, lr, hi2, li2;
                split1(re, hr, lr);
                split1(im, hi2, li2);
                *(__nv_bfloat16*)(g_FwBH + cb + offR) = hr;
                *(__nv_bfloat16*)(g_FwBL + cb + offR) = lr;
                *(__nv_bfloat16*)(g_FwBH + cb + offI) = hi2;
                *(__nv_bfloat16*)(g_FwBL + cb + offI) = li2;
            }
        }
    }
}

// ============ k_dfth_mma2: h-DFT HMMA, 8 bc per block ============
// grid 128, 256 threads. C[64m][256n] = Thf[64x256] . B, n = bcl*32 + (Fr ky | Fi ky).
// smem: AH 0..32768 | AL 32768..65536 | BH 65536..98304 | BL 98304..131072
// epilogue stage C [64][257] floats overlaps 0..65792.
__global__ void __launch_bounds__(256)
k_dfth_mma2() {
    extern __shared__ char smx[];
    const uint32_t sb = smem_u32(smx);
    int t = threadIdx.x;
    int bc0 = blockIdx.x * 8;

    {
        const ulonglong2* srcH = (const ulonglong2*)g_ThfH;
        const ulonglong2* srcL = (const ulonglong2*)g_ThfL;
        ulonglong2* dstH = (ulonglong2*)smx;
        ulonglong2* dstL = (ulonglong2*)(smx + 32768);
        for (int k = t; k < 2048; k += 256) { dstH[k] = srcH[k]; dstL[k] = srcL[k]; }
    }

    const int lane = t & 31;
    const int wrp  = t >> 5;
    const int mt   = wrp & 3;       // m-tile (16 rows of 64)
    const int nh   = wrp >> 2;      // n-half (128 cols of 256)
    const int grp = lane >> 3, rr = lane & 7;
    const int a_m = ((grp & 1) << 3) + rr;
    const int a_k = (grp >> 1) << 3;
    const int b_n = ((grp >> 1) << 3) + rr;
    const int b_k = (grp & 1) << 3;

    float acc[16][4];
#pragma unroll
    for (int i = 0; i < 16; i++)
#pragma unroll
        for (int c = 0; c < 4; c++) acc[i][c] = 0.0f;

    for (int kt = 0; kt < 4; kt++) {
        __syncthreads();
        // stage B: 8 bc x 4KB hi + lo (pure copies from prepped layout)
        {
            const ulonglong2* srcH = (const ulonglong2*)(g_FwBH + (size_t)kt * 4096);
            const ulonglong2* srcL = (const ulonglong2*)(g_FwBL + (size_t)kt * 4096);
            ulonglong2* dstH = (ulonglong2*)(smx + 65536);
            ulonglong2* dstL = (ulonglong2*)(smx + 98304);
            for (int k = t; k < 2048; k += 256) {
                int bcl = k >> 8, j = k & 255;   // 256 u128 per bc-chunk (4KB)
                size_t gi = ((size_t)(bc0 + bcl) * 16384 >> 4) + j;
                dstH[bcl * 256 + j] = srcH[gi];
                dstL[bcl * 256 + j] = srcL[gi];
            }
        }
        __syncthreads();
#pragma unroll
        for (int kc = 0; kc < 4; kc++) {
            int kb = kc * 16;
            uint32_t ah[4], al[4];
            uint32_t aoff = (uint32_t)kt * 8192 +
                            SW128((uint32_t)((mt * 16 + a_m) * 128 + (kb + a_k) * 2));
            ldsm4(ah[0], ah[1], ah[2], ah[3], sb + aoff);
            ldsm4(al[0], al[1], al[2], al[3], sb + 32768 + aoff);
#pragma unroll
            for (int jp = 0; jp < 8; jp++) {
                int nl = nh * 128 + jp * 16 + b_n;
                uint32_t bh[4], bl[4];
                uint32_t boff = (uint32_t)(nl >> 5) * 4096 +
                                SW128((uint32_t)((nl & 31) * 128 + (kb + b_k) * 2));
                ldsm4(bh[0], bh[1], bh[2], bh[3], sb + 65536 + boff);
                ldsm4(bl[0], bl[1], bl[2], bl[3], sb + 98304 + boff);
#pragma unroll
                for (int ntl = 0; ntl < 2; ntl++) {
                    float* c = acc[jp * 2 + ntl];
                    mma16816(c, ah, &bh[ntl * 2]);
                    mma16816(c, ah, &bl[ntl * 2]);
                    mma16816(c, al, &bh[ntl * 2]);
                }
            }
        }
    }

    __syncthreads();
    // stage C [64][257]
    {
        float* stage = (float*)smx;
        int g = lane >> 2, tq = lane & 3;
#pragma unroll
        for (int jp = 0; jp < 8; jp++) {
#pragma unroll
            for (int ntl = 0; ntl < 2; ntl++) {
#pragma unroll
                for (int c = 0; c < 4; c++) {
                    int row = mt * 16 + g + ((c >> 1) << 3);
                    int col = nh * 128 + jp * 16 + ntl * 8 + tq * 2 + (c & 1);
                    stage[row * 257 + col] = acc[jp * 2 + ntl][c];
                }
            }
        }
    }
    __syncthreads();
    {
        const float* stage = (const float*)smx;
#pragma unroll
        for (int i = 0; i < 16; i++) {
            int j = t + i * 256;          // < 4096
            int bcl = j >> 9, r = j & 511;
            int kxi = r >> 4, ky = r & 15;
            int cb = bcl * 32;
            float re = stage[kxi * 257 + cb + ky]        - stage[(32 + kxi) * 257 + cb + 16 + ky];
            float im = stage[(32 + kxi) * 257 + cb + ky] + stage[kxi * 257 + cb + 16 + ky];
            g_Fm[(size_t)(bc0 + bcl) * 512 + r] = make_float2(re, im);
        }
    }
}

// ---------------- channel mixing (R5) ----------------
__global__ void k_mix(int layer) {
    __shared__ float2 Wm[WID * WID];
    __shared__ float2 Fsh[BB * WID];
    int t = threadIdx.x;
    int m = blockIdx.x;
    const float2* wsrc = g_Wt + ((size_t)layer * 512 + m) * 4096;
    for (int k = t; k < 4096; k += 256) Wm[k] = wsrc[k];
    for (int k = t; k < 1024; k += 256) {
        int b = k >> 6, i = k & 63;
        Fsh[k] = g_Fm[(size_t)(b * 64 + i) * 512 + m];
    }
    __syncthreads();
#pragma unroll
    for (int u = 0; u < 4; u++) {
        int outi = t + u * 256;
        int b = outi >> 6, o = outi & 63;
        float sr = 0.f, si = 0.f;
#pragma unroll 8
        for (int i = 0; i < 64; i++) {
            float2 f = Fsh[b * 64 + i];
            float2 w = Wm[i * 64 + o];
            sr = fmaf(f.x, w.x, fmaf(-f.y, w.y, sr));
            si = fmaf(f.x, w.y, fmaf( f.y, w.x, si));
        }
        g_Gm[(size_t)(b * 64 + o) * 512 + m] = make_float2(sr, si);
    }
}

// ============ k_idfth_mma2: inverse h-transform HMMA, 2 bc per block ============
// grid 512, 256 threads. C[256h][64n] = Tih[256x64] . B, n = bcl*32 + (re ky | im ky).
// B rows: n=ky: [Gr; -Gi], n=16+ky: [Gi; Gr] (K=64).
// smem: AH 0..32768 | AL 32768..65536 | BH 65536..73728 | BL 73728..81920
__global__ void __launch_bounds__(256)
k_idfth_mma2() {
    extern __shared__ char smx[];
    const uint32_t sb = smem_u32(smx);
    int t = threadIdx.x;
    int bc0 = blockIdx.x * 2;

    {
        const ulonglong2* srcH = (const ulonglong2*)g_TihH;
        const ulonglong2* srcL = (const ulonglong2*)g_TihL;
        ulonglong2* dstH = (ulonglong2*)smx;
        ulonglong2* dstL = (ulonglong2*)(smx + 32768);
        for (int k = t; k < 2048; k += 256) { dstH[k] = srcH[k]; dstL[k] = srcL[k]; }
    }
    // stage B from g_Gm (2 bc)
    for (int k = t; k < 1024; k += 256) {
        int bcl = k >> 9, r = k & 511;
        int kxi = r >> 4, ky = r & 15;
        float2 g = g_Gm[(size_t)(bc0 + bcl) * 512 + r];
        __nv_bfloat16 hr, lr, hi2, li2, hnr, lnr;
        split1(g.x, hr, lr);         // Gr
        split1(g.y, hi2, li2);       // Gi
        split1(-g.y, hnr, lnr);      // -Gi
        uint32_t base = (uint32_t)bcl * 4096;
        uint32_t o_rk  = base + SW128((uint32_t)(ky * 128 + kxi * 2));
        uint32_t o_rni = base + SW128((uint32_t)(ky * 128 + (32 + kxi) * 2));
        uint32_t o_ik  = base + SW128((uint32_t)((16 + ky) * 128 + kxi * 2));
        uint32_t o_ir  = base + SW128((uint32_t)((16 + ky) * 128 + (32 + kxi) * 2));
        *(__nv_bfloat16*)(smx + 65536 + o_rk)  = hr;
        *(__nv_bfloat16*)(smx + 73728 + o_rk)  = lr;
        *(__nv_bfloat16*)(smx + 65536 + o_rni) = hnr;
        *(__nv_bfloat16*)(smx + 73728 + o_rni) = lnr;
        *(__nv_bfloat16*)(smx + 65536 + o_ik)  = hi2;
        *(__nv_bfloat16*)(smx + 73728 + o_ik)  = li2;
        *(__nv_bfloat16*)(smx + 65536 + o_ir)  = hr;
        *(__nv_bfloat16*)(smx + 73728 + o_ir)  = lr;
    }
    __syncthreads();

    const int lane = t & 31;
    const int wrp  = t >> 5;
    const int hbase = wrp * 32;     // warp covers m-tiles wrp*2, wrp*2+1
    const int grp = lane >> 3, rr = lane & 7;
    const int a_m = ((grp & 1) << 3) + rr;
    const int a_k = (grp >> 1) << 3;
    const int b_n = ((grp >> 1) << 3) + rr;
    const int b_k = (grp & 1) << 3;

    float acc[2][8][4];
#pragma unroll
    for (int mt = 0; mt < 2; mt++)
#pragma unroll
        for (int n8 = 0; n8 < 8; n8++)
#pragma unroll
            for (int c = 0; c < 4; c++) acc[mt][n8][c] = 0.0f;

#pragma unroll
    for (int kc = 0; kc < 4; kc++) {
        int kb = kc * 16;
        uint32_t ah[2][4], al[2][4];
#pragma unroll
        for (int mt = 0; mt < 2; mt++) {
            uint32_t aoff = SW128((uint32_t)((hbase + mt * 16 + a_m) * 128 + (kb + a_k) * 2));
            ldsm4(ah[mt][0], ah[mt][1], ah[mt][2], ah[mt][3], sb + aoff);
            ldsm4(al[mt][0], al[mt][1], al[mt][2], al[mt][3], sb + 32768 + aoff);
        }
#pragma unroll
        for (int jp = 0; jp < 4; jp++) {
            int nl = jp * 16 + b_n;
            uint32_t bh[4], bl[4];
            uint32_t boff = (uint32_t)(nl >> 5) * 4096 +
                            SW128((uint32_t)((nl & 31) * 128 + (kb + b_k) * 2));
            ldsm4(bh[0], bh[1], bh[2], bh[3], sb + 65536 + boff);
            ldsm4(bl[0], bl[1], bl[2], bl[3], sb + 73728 + boff);
#pragma unroll
            for (int mt = 0; mt < 2; mt++) {
#pragma unroll
                for (int ntl = 0; ntl < 2; ntl++) {
                    float* c = acc[mt][jp * 2 + ntl];
                    mma16816(c, ah[mt], &bh[ntl * 2]);
                    mma16816(c, ah[mt], &bl[ntl * 2]);
                    mma16816(c, al[mt], &bh[ntl * 2]);
                }
            }
        }
    }

    // write fragments: within each bc strip (4 n8), re tiles n8&3<2, im at +2
    int g = lane >> 2, tq = lane & 3;
#pragma unroll
    for (int mt = 0; mt < 2; mt++) {
#pragma unroll
        for (int bcl = 0; bcl < 2; bcl++) {
#pragma unroll
            for (int a = 0; a < 2; a++) {
                int n8re = bcl * 4 + a;
#pragma unroll
                for (int c = 0; c < 4; c++) {
                    int h  = hbase + mt * 16 + g + ((c >> 1) << 3);
                    int ky = a * 8 + tq * 2 + (c & 1);
                    float re = acc[mt][n8re][c];
                    float im = acc[mt][n8re + 2][c];
                    g_Gw[((size_t)(bc0 + bcl) * 256 + h) * 16 + ky] = make_float2(re, im);
                }
            }
        }
    }
}

// ============ k_fused_mma v2 (R15, verified) ============
__global__ void __launch_bounds__(256)
k_fused_mma(const float* __restrict__ hin, float* __restrict__ hout,
            int layer, const float* __restrict__ pwb, int dogelu) {
    extern __shared__ char smx[];
    const uint32_t sb = smem_u32(smx);
    int t = threadIdx.x;
    int b = blockIdx.x >> 8, row = blockIdx.x & 255;

    const int lane = t & 31;
    const int wrp  = t >> 5;
    const int pxb  = wrp * 32;
    const int grp = lane >> 3, rr = lane & 7;
    const int a_m = ((grp & 1) << 3) + rr;
    const int a_k = (grp >> 1) << 3;
    const int b_n = ((grp >> 1) << 3) + rr;
    const int b_k = (grp & 1) << 3;

    float acc[2][8][4];
#pragma unroll
    for (int mt = 0; mt < 2; mt++)
#pragma unroll
        for (int n8 = 0; n8 < 8; n8++)
#pragma unroll
            for (int c = 0; c < 4; c++) acc[mt][n8][c] = 0.0f;

    // ---- Phase A staging: synth T tiles + Gd + bias ----
    {
        const ulonglong2* srcH = (const ulonglong2*)g_TsbH;
        const ulonglong2* srcL = (const ulonglong2*)g_TsbL;
        ulonglong2* dstH = (ulonglong2*)smx;
        ulonglong2* dstL = (ulonglong2*)(smx + 16384);
        for (int k = t; k < 1024; k += 256) { dstH[k] = srcH[k]; dstL[k] = srcL[k]; }
    }
    for (int k = t; k < 1024; k += 256) {
        int och = k >> 4, ky = k & 15;
        float2 g = g_Gw[(((size_t)(b * 64 + och)) * 256 + row) * 16 + ky];
        float vx = (ky == 0) ? g.x : 2.0f * g.x;
        float vy = (ky == 0) ? 0.0f : -2.0f * g.y;
        __nv_bfloat16 hx, lx, hy, ly;
        split1(vx, hx, lx);
        split1(vy, hy, ly);
        uint32_t off1 = SW64((uint32_t)(och * 64 + ky * 2));
        uint32_t off2 = SW64((uint32_t)(och * 64 + (16 + ky) * 2));
        *(__nv_bfloat16*)(smx + 32768 + off1) = hx;
        *(__nv_bfloat16*)(smx + 36864 + off1) = lx;
        *(__nv_bfloat16*)(smx + 32768 + off2) = hy;
        *(__nv_bfloat16*)(smx + 36864 + off2) = ly;
    }
    if (t < 64) ((float*)(smx + 81920))[t] = pwb[t];
    __syncthreads();

    // ---- Phase A MMAs: synthesis, K=32, SW64 tiles ----
#pragma unroll
    for (int kt = 0; kt < 2; kt++) {
        int kb = kt * 16;
        uint32_t ah[2][4], al[2][4];
#pragma unroll
        for (int mt = 0; mt < 2; mt++) {
            uint32_t aoff = SW64((uint32_t)((pxb + mt * 16 + a_m) * 64 + (kb + a_k) * 2));
            ldsm4(ah[mt][0], ah[mt][1], ah[mt][2], ah[mt][3], sb + aoff);
            ldsm4(al[mt][0], al[mt][1], al[mt][2], al[mt][3], sb + 16384 + aoff);
        }
#pragma unroll
        for (int jp = 0; jp < 4; jp++) {
            int nb = jp * 16;
            uint32_t bh[4], bl[4];
            uint32_t boff = SW64((uint32_t)((nb + b_n) * 64 + (kb + b_k) * 2));
            ldsm4(bh[0], bh[1], bh[2], bh[3], sb + 32768 + boff);
            ldsm4(bl[0], bl[1], bl[2], bl[3], sb + 36864 + boff);
#pragma unroll
            for (int mt = 0; mt < 2; mt++) {
#pragma unroll
                for (int ntl = 0; ntl < 2; ntl++) {
                    float* c = acc[mt][jp * 2 + ntl];
                    mma16816(c, ah[mt], &bh[ntl * 2]);
                    mma16816(c, ah[mt], &bl[ntl * 2]);
                    mma16816(c, al[mt], &bh[ntl * 2]);
                }
            }
        }
    }
    __syncthreads();

    // ---- Phase B staging: X hi/lo + W hi/lo ----
    {
        const float* xp = hin + ((size_t)(b * 64) << 16) + row * 256 + t;
#pragma unroll
        for (int i2 = 0; i2 < 32; i2++) {
            float xa = xp[(size_t)(2 * i2) << 16];
            float xb = xp[(size_t)(2 * i2 + 1) << 16];
            uint32_t hp, lp;
            split2(xa, xb, hp, lp);
            uint32_t off = SW128((uint32_t)(t * 128 + i2 * 4));
            *(uint32_t*)(smx + off)         = hp;
            *(uint32_t*)(smx + 32768 + off) = lp;
        }
    }
    {
        const ulonglong2* srcH = (const ulonglong2*)(g_WbH + layer * 8192);
        const ulonglong2* srcL = (const ulonglong2*)(g_WbL + layer * 8192);
        ulonglong2* dstH = (ulonglong2*)(smx + 65536);
        ulonglong2* dstL = (ulonglong2*)(smx + 73728);
        for (int k = t; k < 512; k += 256) { dstH[k] = srcH[k]; dstL[k] = srcL[k]; }
    }
    __syncthreads();

    // ---- Phase B MMAs: conv, K=64, SW128 tiles ----
#pragma unroll
    for (int kt = 0; kt < 4; kt++) {
        int kb = kt * 16;
        uint32_t ah[2][4], al[2][4];
#pragma unroll
        for (int mt = 0; mt < 2; mt++) {
            uint32_t aoff = SW128((uint32_t)((pxb + mt * 16 + a_m) * 128 + (kb + a_k) * 2));
            ldsm4(ah[mt][0], ah[mt][1], ah[mt][2], ah[mt][3], sb + aoff);
            ldsm4(al[mt][0], al[mt][1], al[mt][2], al[mt][3], sb + 32768 + aoff);
        }
#pragma unroll
        for (int jp = 0; jp < 4; jp++) {
            int nb = jp * 16;
            uint32_t bh[4], bl[4];
            uint32_t boff = SW128((uint32_t)((nb + b_n) * 128 + (kb + b_k) * 2));
            ldsm4(bh[0], bh[1], bh[2], bh[3], sb + 65536 + boff);
            ldsm4(bl[0], bl[1], bl[2], bl[3], sb + 73728 + boff);
#pragma unroll
            for (int mt = 0; mt < 2; mt++) {
#pragma unroll
                for (int ntl = 0; ntl < 2; ntl++) {
                    float* c = acc[mt][jp * 2 + ntl];
                    mma16816(c, ah[mt], &bh[ntl * 2]);
                    mma16816(c, ah[mt], &bl[ntl * 2]);
                    mma16816(c, al[mt], &bh[ntl * 2]);
                }
            }
        }
    }

    // ---- epilogue ----
    __syncthreads();
    {
        float* stage = (float*)smx;
        const float* bsh = (const float*)(smx + 81920);
        int g = lane >> 2, tq = lane & 3;
#pragma unroll
        for (int mt = 0; mt < 2; mt++) {
            int px0 = pxb + mt * 16 + g;
#pragma unroll
            for (int n8 = 0; n8 < 8; n8++) {
                int och = n8 * 8 + tq * 2;
                float b0 = bsh[och], b1 = bsh[och + 1];
                float v00 = acc[mt][n8][0] + b0;
                float v01 = acc[mt][n8][1] + b1;
                float v10 = acc[mt][n8][2] + b0;
                float v11 = acc[mt][n8][3] + b1;
                if (dogelu) {
                    v00 = gelu_fast(v00); v01 = gelu_fast(v01);
                    v10 = gelu_fast(v10); v11 = gelu_fast(v11);
                }
                stage[och * 260 + px0]           = v00;
                stage[(och + 1) * 260 + px0]     = v01;
                stage[och * 260 + px0 + 8]       = v10;
                stage[(och + 1) * 260 + px0 + 8] = v11;
            }
        }
    }
    __syncthreads();
    {
        const float* stage = (const float*)smx;
        float* outp = hout + ((size_t)(b * 64) << 16) + row * 256 + t;
#pragma unroll 8
        for (int i = 0; i < 64; i++)
            outp[(size_t)i << 16] = stage[i * 260 + t];
    }
}

// ============ k_final_mma (R13, verified) ============
__global__ void __launch_bounds__(512)
k_final_mma(const float* __restrict__ hin, float* __restrict__ out,
            const float* __restrict__ b1, const float* __restrict__ w2,
            const float* __restrict__ b2) {
    extern __shared__ char smx[];
    const uint32_t sb = smem_u32(smx);
    int t = threadIdx.x;
    int b = blockIdx.x >> 8, row = blockIdx.x & 255;

    size_t base = ((size_t)(b * 64) << 16) + (size_t)row * 256;
    for (int k = t; k < 8192; k += 512) {
        int px = k & 255, i2 = k >> 8;
        float xa = hin[base + ((size_t)(2 * i2) << 16) + px];
        float xb = hin[base + ((size_t)(2 * i2 + 1) << 16) + px];
        uint32_t hp, lp;
        split2(xa, xb, hp, lp);
        uint32_t off = SW128((uint32_t)(px * 128 + i2 * 4));
        *(uint32_t*)(smx + off)         = hp;
        *(uint32_t*)(smx + 32768 + off) = lp;
    }
    {
        const ulonglong2* srcH = (const ulonglong2*)g_W1bH;
        const ulonglong2* srcL = (const ulonglong2*)g_W1bL;
        ulonglong2* dstH = (ulonglong2*)(smx + 65536);
        ulonglong2* dstL = (ulonglong2*)(smx + 81920);
        for (int k = t; k < 1024; k += 512) { dstH[k] = srcH[k]; dstL[k] = srcL[k]; }
    }
    {
        ull* w2t = (ull*)(smx + 133120);
        for (int k = t; k < FCH * 10; k += 512) {
            int o2 = k >> 7, j = k & 127;
            w2t[j * 10 + o2] = pk(w2[(2 * o2) * FCH + j], w2[(2 * o2 + 1) * FCH + j]);
        }
    }
    if (t < FCH) ((float*)(smx + 143360))[t] = b1[t];
    if (t < 10)  ((ull*)(smx + 143872))[t] = pk(b2[2 * t], b2[2 * t + 1]);
    __syncthreads();

    const int lane = t & 31;
    const int wrp  = t >> 5;
    const int pxb  = wrp * 16;
    const int grp = lane >> 3, rr = lane & 7;
    const int a_m = ((grp & 1) << 3) + rr;
    const int a_k = (grp >> 1) << 3;
    const int b_n = ((grp >> 1) << 3) + rr;
    const int b_k = (grp & 1) << 3;

    float acc[64];
#pragma unroll
    for (int i = 0; i < 64; i++) acc[i] = 0.0f;

#pragma unroll
    for (int kt = 0; kt < 4; kt++) {
        int kb = kt * 16;
        uint32_t ah[4], al[4];
        uint32_t aoff = SW128((uint32_t)((pxb + a_m) * 128 + (kb + a_k) * 2));
        ldsm4(ah[0], ah[1], ah[2], ah[3], sb + aoff);
        ldsm4(al[0], al[1], al[2], al[3], sb + 32768 + aoff);
#pragma unroll
        for (int jp = 0; jp < 8; jp++) {
            uint32_t bh[4], bl[4];
            uint32_t boff = SW128((uint32_t)((jp * 16 + b_n) * 128 + (kb + b_k) * 2));
            ldsm4(bh[0], bh[1], bh[2], bh[3], sb + 65536 + boff);
            ldsm4(bl[0], bl[1], bl[2], bl[3], sb + 81920 + boff);
#pragma unroll
            for (int ntl = 0; ntl < 2; ntl++) {
                float* c = &acc[(jp * 2 + ntl) * 4];
                mma16816(c, ah, &bh[ntl * 2]);
                mma16816(c, ah, &bl[ntl * 2]);
                mma16816(c, al, &bh[ntl * 2]);
            }
        }
    }

    __syncthreads();
    {
        float* stage = (float*)smx;
        const float* b1sh = (const float*)(smx + 143360);
        int g = lane >> 2, tq = lane & 3;
        int px0 = pxb + g;
#pragma unroll
        for (int n8 = 0; n8 < 16; n8++) {
            int j0 = n8 * 8 + tq * 2;
            float bb0 = b1sh[j0], bb1 = b1sh[j0 + 1];
            stage[j0 * 260 + px0]           = gelu_fast(acc[n8 * 4 + 0] + bb0);
            stage[(j0 + 1) * 260 + px0]     = gelu_fast(acc[n8 * 4 + 1] + bb1);
            stage[j0 * 260 + px0 + 8]       = gelu_fast(acc[n8 * 4 + 2] + bb0);
            stage[(j0 + 1) * 260 + px0 + 8] = gelu_fast(acc[n8 * 4 + 3] + bb1);
        }
    }
    __syncthreads();
    {
        const float* stage = (const float*)smx;
        const ull* w2t = (const ull*)(smx + 133120);
        const ull* b2p = (const ull*)(smx + 143872);
        int px = t & 255;
        int oh = t >> 8;
        ull a5[5];
#pragma unroll
        for (int k = 0; k < 5; k++) a5[k] = b2p[oh * 5 + k];
        for (int j = 0; j < FCH; j++) {
            float hv = stage[j * 260 + px];
            ull hh = pk(hv, hv);
            const ull* wp = &w2t[j * 10 + oh * 5];
#pragma unroll
            for (int k = 0; k < 5; k++) a5[k] = ff2(hh, wp[k], a5[k]);
        }
        size_t sp = (size_t)row * 256 + px;
#pragma unroll
        for (int k = 0; k < 5; k++) {
            int o2 = oh * 5 + k;
            float2 a = upk(a5[k]);
            out[((size_t)(b * CO + 2 * o2) << 16) + sp]     = a.x;
            out[((size_t)(b * CO + 2 * o2 + 1) << 16) + sp] = a.y;
        }
    }
}

// ---------------- orchestration ----------------
extern "C" void kernel_launch(void* const* d_in, const int* in_sizes, int n_in,
                              void* d_out, int out_size) {
    const float* x    = (const float*)d_in[0];
    const float* w1r  = (const float*)d_in[1];
    const float* w1i  = (const float*)d_in[2];
    const float* w2r  = (const float*)d_in[3];
    const float* w2i  = (const float*)d_in[4];
    const float* pww  = (const float*)d_in[5];
    const float* pwb  = (const float*)d_in[6];
    const float* fc0w = (const float*)d_in[7];
    const float* fc0b = (const float*)d_in[8];
    const float* fc1w = (const float*)d_in[9];
    const float* fc1b = (const float*)d_in[10];
    const float* fc2w = (const float*)d_in[11];
    const float* fc2b = (const float*)d_in[12];
    float* out = (float*)d_out;

    cudaFuncSetAttribute(k_dftw_mma,   cudaFuncAttributeMaxDynamicSharedMemorySize, 98304);
    cudaFuncSetAttribute(k_dfth_mma2,  cudaFuncAttributeMaxDynamicSharedMemorySize, 131072);
    cudaFuncSetAttribute(k_idfth_mma2, cudaFuncAttributeMaxDynamicSharedMemorySize, 81920);
    cudaFuncSetAttribute(k_fused_mma,  cudaFuncAttributeMaxDynamicSharedMemorySize, 82176);
    cudaFuncSetAttribute(k_final_mma,  cudaFuncAttributeMaxDynamicSharedMemorySize, 143952);

    void *p0, *p1;
    cudaGetSymbolAddress(&p0, g_h0);
    cudaGetSymbolAddress(&p1, g_h1);
    float* hb[2] = {(float*)p0, (float*)p1};

    k_twiddle<<<32, 256>>>();
    k_prep2<<<32, 256>>>(fc1w);
    k_prep3<<<64, 256>>>();
    k_wbprep<<<NLAY * 4096 / 256, 256>>>(pww);
    k_wt<<<(NLAY * 512 * WID * WID) / 256, 256>>>(w1r, w1i, w2r, w2i);
    k_fc0<<<NPIX / 256, 256>>>(x, fc0w, fc0b);

    for (int l = 0; l < NLAY; l++) {
        const float* hi = hb[l & 1];
        float*       ho = hb[(l + 1) & 1];
        k_dftw_mma<<<1024, 256, 98304>>>(hi);
        k_dfth_mma2<<<128, 256, 131072>>>();
        k_mix<<<512, 256>>>(l);
        k_idfth_mma2<<<512, 256, 81920>>>();
        k_fused_mma<<<4096, 256, 82176>>>(hi, ho, l, pwb + (size_t)l * WID,
                                          (l < NLAY - 1) ? 1 : 0);
    }
    k_final_mma<<<4096, 512, 143952>>>(hb[0], out, fc1b, fc2w, fc2b);
}